// round 2
// baseline (speedup 1.0000x reference)
#include <cuda_runtime.h>
#include <cuda_bf16.h>
#include <cstdint>

#define N_NODES 20000
#define READ_LEN 64
#define N_EDGES 320000
#define DIM 128
#define KSZ 20
#define CONV_T (READ_LEN - KSZ + 1)
#define N_LAYERS 4
#define EPS_BN 1e-5f
#define EPS_AGG 1e-6f

typedef unsigned long long ull;

// packed fp32x2 FMA (Blackwell): d = a*b + d elementwise on packed pairs
#define FMA2(d, a, b) asm("fma.rn.f32x2 %0, %1, %2, %0;" : "+l"(d) : "l"(a), "l"(b))
#define PACK2(d, x)   asm("mov.b64 %0, {%1, %1};" : "=l"(d) : "f"(x))
#define UNPACK2(lo, hi, p) asm("mov.b64 {%0, %1}, %2;" : "=f"(lo), "=f"(hi) : "l"(p))

// ---------------- device scratch (no allocations allowed) ----------------
__device__ float g_h[N_NODES * DIM];
__device__ float g_e[(size_t)N_EDGES * DIM];
__device__ float g_ehat[(size_t)N_EDGES * DIM];
__device__ float g_Ah[N_NODES * DIM];
__device__ float g_Bh[N_NODES * DIM];
__device__ float g_Dh[N_NODES * DIM];
__device__ float g_Eh[N_NODES * DIM];
__device__ float g_t[N_NODES * DIM];
__device__ float g_wsum[4 * KSZ * DIM];
__device__ float g_stats[2 * DIM];
__device__ float g_bn_scale[DIM];
__device__ float g_bn_shift[DIM];
__device__ int g_cnt[N_NODES];
__device__ int g_off[N_NODES + 1];
__device__ int g_cur[N_NODES];
__device__ int g_eids[N_EDGES];

// ---------------- sequence encoder ----------------
// wsum[b][k][d] = sum_c emb[b][c] * conv_w[d][c][k]
__global__ void k_wsum(const float* __restrict__ emb, const float* __restrict__ cw)
{
    int idx = blockIdx.x * 256 + threadIdx.x;
    if (idx >= 4 * KSZ * DIM) return;
    int d = idx & 127;
    int bk = idx >> 7;
    int k = bk % KSZ, b = bk / KSZ;
    float s = 0.f;
#pragma unroll
    for (int c = 0; c < 3; c++) s += emb[b * 3 + c] * cw[d * 3 * KSZ + c * KSZ + k];
    g_wsum[idx] = s;
}

__global__ __launch_bounds__(512) void k_seq(const int* __restrict__ reads,
                                             const float* __restrict__ conv_b)
{
    __shared__ float sw[4 * KSZ * DIM];
    __shared__ int sbase[4][READ_LEN];
    int tid = threadIdx.x;
    for (int i = tid; i < 4 * KSZ * DIM; i += 512) sw[i] = g_wsum[i];
    if (tid < 4 * READ_LEN) {
        int gi = tid >> 6, l = tid & 63;
        int n = blockIdx.x * 4 + gi;
        sbase[gi][l] = reads[n * READ_LEN + l] * (KSZ * DIM);
    }
    __syncthreads();
    int gi = tid >> 7, d = tid & 127;
    int n = blockIdx.x * 4 + gi;
    const int* rb = sbase[gi];
    const float* swd = sw + d;
    float m = -3.4e38f;
    for (int t = 0; t < CONV_T; t++) {
        float s = 0.f;
#pragma unroll
        for (int k = 0; k < KSZ; k++) s += swd[rb[t + k] + (k << 7)];
        m = fmaxf(m, s);
    }
    g_h[n * DIM + d] = fmaxf(m + conv_b[d], 0.f);
}

// ---------------- edge encoder ----------------
__global__ __launch_bounds__(128) void k_edge_enc(const float* __restrict__ sim,
                                                  const float* __restrict__ len,
                                                  const float* __restrict__ ew,
                                                  const float* __restrict__ eb)
{
    int d = threadIdx.x;
    float w0 = ew[d * 2], w1 = ew[d * 2 + 1], b = eb[d];
    int e0 = blockIdx.x * 32;
#pragma unroll 4
    for (int j = 0; j < 32; j++) {
        int eid = e0 + j;
        g_e[(size_t)eid * DIM + d] = fmaf(sim[eid], w0, fmaf(len[eid], w1, b));
    }
}

// ---------------- CSR build by dst ----------------
__global__ void k_csr_zero()
{
    int i = blockIdx.x * 256 + threadIdx.x;
    if (i < N_NODES) g_cnt[i] = 0;
}
__global__ void k_hist(const int* __restrict__ dst)
{
    int i = blockIdx.x * 256 + threadIdx.x;
    if (i < N_EDGES) atomicAdd(&g_cnt[dst[i]], 1);
}
__global__ __launch_bounds__(1024) void k_scan()
{
    __shared__ int sd[1024];
    int tid = threadIdx.x;
    int carry = 0;
    for (int base = 0; base < N_NODES; base += 1024) {
        int i = base + tid;
        int v = (i < N_NODES) ? g_cnt[i] : 0;
        __syncthreads();
        sd[tid] = v;
        __syncthreads();
        for (int ofs = 1; ofs < 1024; ofs <<= 1) {
            int t = (tid >= ofs) ? sd[tid - ofs] : 0;
            __syncthreads();
            sd[tid] += t;
            __syncthreads();
        }
        if (i < N_NODES) {
            int ex = carry + sd[tid] - v;
            g_off[i] = ex;
            g_cur[i] = ex;
        }
        carry += sd[1023];
    }
    if (tid == 0) g_off[N_NODES] = carry;
}
__global__ void k_scatter(const int* __restrict__ dst)
{
    int i = blockIdx.x * 256 + threadIdx.x;
    if (i < N_EDGES) {
        int p = atomicAdd(&g_cur[dst[i]], 1);
        g_eids[p] = i;
    }
}

// ---------------- stats ----------------
__global__ void k_zero_stats()
{
    if (threadIdx.x < 256) g_stats[threadIdx.x] = 0.f;
}
__global__ __launch_bounds__(128) void k_bn_final(const float* __restrict__ g,
                                                  const float* __restrict__ b,
                                                  float invc)
{
    int d = threadIdx.x;
    float s = g_stats[d], sq = g_stats[128 + d];
    float mean = s * invc;
    float var = sq * invc - mean * mean;
    float sc = g[d] * rsqrtf(var + EPS_BN);
    g_bn_scale[d] = sc;
    g_bn_shift[d] = b[d] - mean * sc;
    g_stats[d] = 0.f;
    g_stats[128 + d] = 0.f;
}

// ---------------- node GEMM: Ah,Bh,Dh,Eh = h @ W.T + bias ----------------
__global__ __launch_bounds__(256, 2) void k_node_gemm(
    const float* __restrict__ Wa, const float* __restrict__ Wb,
    const float* __restrict__ Wd, const float* __restrict__ We,
    const float* __restrict__ Ba, const float* __restrict__ Bb_,
    const float* __restrict__ Bd, const float* __restrict__ Be)
{
    const float* Wp[4] = {Wa, Wb, Wd, We};
    const float* Bp[4] = {Ba, Bb_, Bd, Be};
    float* Op[4] = {g_Ah, g_Bh, g_Dh, g_Eh};
    extern __shared__ float sm[];
    float* Ws = sm;               // [128][132]
    float* Hs = sm + 128 * 132;   // [128][68]
    int tid = threadIdx.x;
    int n0 = blockIdx.x * 64;
    int mlim = N_NODES - n0;
    if (mlim > 64) mlim = 64;

    for (int i = tid; i < 64 * 128; i += 256) {
        int m = i >> 7, k = i & 127;
        Hs[k * 68 + m] = (m < mlim) ? g_h[(n0 + m) * 128 + k] : 0.f;
    }
    int tx = tid & 31, ty = tid >> 5;
    const float* Erow = Hs + (ty << 3);
    const float* Wrow = Ws + (tx << 2);

    for (int mat = 0; mat < 4; mat++) {
        __syncthreads();
        const float* W = Wp[mat];
        for (int i = tid; i < 128 * 128; i += 256) {
            int d = i >> 7, k = i & 127;
            Ws[k * 132 + d] = W[i];
        }
        __syncthreads();
        ull acc[16];
#pragma unroll
        for (int i = 0; i < 16; i++) acc[i] = 0ull;
#pragma unroll 4
        for (int k = 0; k < 128; k++) {
            ulonglong2 a01 = *(const ulonglong2*)(Erow + k * 68);
            ulonglong2 a23 = *(const ulonglong2*)(Erow + k * 68 + 4);
            float4 w4 = *(const float4*)(Wrow + k * 132);
            ull b0, b1, b2, b3;
            PACK2(b0, w4.x); PACK2(b1, w4.y); PACK2(b2, w4.z); PACK2(b3, w4.w);
            FMA2(acc[0], a01.x, b0); FMA2(acc[1], a01.x, b1);
            FMA2(acc[2], a01.x, b2); FMA2(acc[3], a01.x, b3);
            FMA2(acc[4], a01.y, b0); FMA2(acc[5], a01.y, b1);
            FMA2(acc[6], a01.y, b2); FMA2(acc[7], a01.y, b3);
            FMA2(acc[8], a23.x, b0); FMA2(acc[9], a23.x, b1);
            FMA2(acc[10], a23.x, b2); FMA2(acc[11], a23.x, b3);
            FMA2(acc[12], a23.y, b0); FMA2(acc[13], a23.y, b1);
            FMA2(acc[14], a23.y, b2); FMA2(acc[15], a23.y, b3);
        }
        float4 bias = *(const float4*)(Bp[mat] + (tx << 2));
        float* Out = Op[mat];
#pragma unroll
        for (int mp = 0; mp < 4; mp++) {
            float lo0, hi0, lo1, hi1, lo2, hi2, lo3, hi3;
            UNPACK2(lo0, hi0, acc[mp * 4 + 0]);
            UNPACK2(lo1, hi1, acc[mp * 4 + 1]);
            UNPACK2(lo2, hi2, acc[mp * 4 + 2]);
            UNPACK2(lo3, hi3, acc[mp * 4 + 3]);
            int ml = (ty << 3) + mp * 2;
            if (ml < mlim) {
                float4 v = {lo0 + bias.x, lo1 + bias.y, lo2 + bias.z, lo3 + bias.w};
                *(float4*)(Out + (n0 + ml) * 128 + (tx << 2)) = v;
            }
            if (ml + 1 < mlim) {
                float4 v = {hi0 + bias.x, hi1 + bias.y, hi2 + bias.z, hi3 + bias.w};
                *(float4*)(Out + (n0 + ml + 1) * 128 + (tx << 2)) = v;
            }
        }
    }
}

// ---------------- edge pass1: ehat = e @ Cw.T + Cb + Dh[dst] + Eh[src]; BN stats ----------------
__global__ __launch_bounds__(256, 2) void k_edge_pass1(const float* __restrict__ Cw,
                                                       const float* __restrict__ Cb,
                                                       const int* __restrict__ src,
                                                       const int* __restrict__ dst)
{
    extern __shared__ float sm[];
    float* Ws = sm;               // [128][132]
    float* Es = sm + 128 * 132;   // [128][68]
    int* s_src = (int*)(Es + 128 * 68);
    int* s_dst = s_src + 64;
    float* ssum = (float*)(s_dst + 64);
    float* ssq = ssum + 128;
    int tid = threadIdx.x;
    int e0 = blockIdx.x * 64;

    for (int i = tid; i < 128 * 128; i += 256) {
        int d = i >> 7, k = i & 127;
        Ws[k * 132 + d] = Cw[i];
    }
    for (int i = tid; i < 64 * 128; i += 256) {
        int m = i >> 7, k = i & 127;
        Es[k * 68 + m] = g_e[(size_t)(e0 + m) * 128 + k];
    }
    if (tid < 64) { s_src[tid] = src[e0 + tid]; s_dst[tid] = dst[e0 + tid]; }
    if (tid < 128) { ssum[tid] = 0.f; ssq[tid] = 0.f; }
    __syncthreads();

    int tx = tid & 31, ty = tid >> 5;
    const float* Erow = Es + (ty << 3);
    const float* Wrow = Ws + (tx << 2);
    ull acc[16];
#pragma unroll
    for (int i = 0; i < 16; i++) acc[i] = 0ull;
#pragma unroll 4
    for (int k = 0; k < 128; k++) {
        ulonglong2 a01 = *(const ulonglong2*)(Erow + k * 68);
        ulonglong2 a23 = *(const ulonglong2*)(Erow + k * 68 + 4);
        float4 w4 = *(const float4*)(Wrow + k * 132);
        ull b0, b1, b2, b3;
        PACK2(b0, w4.x); PACK2(b1, w4.y); PACK2(b2, w4.z); PACK2(b3, w4.w);
        FMA2(acc[0], a01.x, b0); FMA2(acc[1], a01.x, b1);
        FMA2(acc[2], a01.x, b2); FMA2(acc[3], a01.x, b3);
        FMA2(acc[4], a01.y, b0); FMA2(acc[5], a01.y, b1);
        FMA2(acc[6], a01.y, b2); FMA2(acc[7], a01.y, b3);
        FMA2(acc[8], a23.x, b0); FMA2(acc[9], a23.x, b1);
        FMA2(acc[10], a23.x, b2); FMA2(acc[11], a23.x, b3);
        FMA2(acc[12], a23.y, b0); FMA2(acc[13], a23.y, b1);
        FMA2(acc[14], a23.y, b2); FMA2(acc[15], a23.y, b3);
    }

    float4 cb = *(const float4*)(Cb + (tx << 2));
    float ls0 = 0.f, ls1 = 0.f, ls2 = 0.f, ls3 = 0.f;
    float lq0 = 0.f, lq1 = 0.f, lq2 = 0.f, lq3 = 0.f;
#pragma unroll
    for (int mp = 0; mp < 4; mp++) {
        float lo0, hi0, lo1, hi1, lo2, hi2, lo3, hi3;
        UNPACK2(lo0, hi0, acc[mp * 4 + 0]);
        UNPACK2(lo1, hi1, acc[mp * 4 + 1]);
        UNPACK2(lo2, hi2, acc[mp * 4 + 2]);
        UNPACK2(lo3, hi3, acc[mp * 4 + 3]);
#pragma unroll
        for (int half = 0; half < 2; half++) {
            int ml = (ty << 3) + mp * 2 + half;
            float v0 = half ? hi0 : lo0, v1 = half ? hi1 : lo1;
            float v2 = half ? hi2 : lo2, v3 = half ? hi3 : lo3;
            int sr = s_src[ml], dd = s_dst[ml];
            float4 dh = *(const float4*)(g_Dh + dd * 128 + (tx << 2));
            float4 eh = *(const float4*)(g_Eh + sr * 128 + (tx << 2));
            float4 v;
            v.x = v0 + cb.x + dh.x + eh.x;
            v.y = v1 + cb.y + dh.y + eh.y;
            v.z = v2 + cb.z + dh.z + eh.z;
            v.w = v3 + cb.w + dh.w + eh.w;
            *(float4*)(g_ehat + (size_t)(e0 + ml) * 128 + (tx << 2)) = v;
            ls0 += v.x; lq0 += v.x * v.x;
            ls1 += v.y; lq1 += v.y * v.y;
            ls2 += v.z; lq2 += v.z * v.z;
            ls3 += v.w; lq3 += v.w * v.w;
        }
    }
    int d0 = tx << 2;
    atomicAdd(&ssum[d0 + 0], ls0); atomicAdd(&ssq[d0 + 0], lq0);
    atomicAdd(&ssum[d0 + 1], ls1); atomicAdd(&ssq[d0 + 1], lq1);
    atomicAdd(&ssum[d0 + 2], ls2); atomicAdd(&ssq[d0 + 2], lq2);
    atomicAdd(&ssum[d0 + 3], ls3); atomicAdd(&ssq[d0 + 3], lq3);
    __syncthreads();
    if (tid < 128) {
        atomicAdd(&g_stats[tid], ssum[tid]);
        atomicAdd(&g_stats[128 + tid], ssq[tid]);
    }
}

// ---------------- e += relu(bn(ehat)) ----------------
__global__ __launch_bounds__(256) void k_edge_update()
{
    int i = blockIdx.x * 256 + threadIdx.x;   // over E*32 float4s
    int d4 = (i & 31) << 2;
    float4 sc = *(const float4*)(g_bn_scale + d4);
    float4 sh = *(const float4*)(g_bn_shift + d4);
    float4 x = ((const float4*)g_ehat)[i];
    float4 ev = ((const float4*)g_e)[i];
    ev.x += fmaxf(fmaf(x.x, sc.x, sh.x), 0.f);
    ev.y += fmaxf(fmaf(x.y, sc.y, sh.y), 0.f);
    ev.z += fmaxf(fmaf(x.z, sc.z, sh.z), 0.f);
    ev.w += fmaxf(fmaf(x.w, sc.w, sh.w), 0.f);
    ((float4*)g_e)[i] = ev;
}

// ---------------- aggregation: t = Ah + segsum(sigma*Bh[src]) / (segsum(sigma)+eps) ----------------
__global__ __launch_bounds__(128) void k_aggregate(const int* __restrict__ src)
{
    int n = blockIdx.x;
    int d = threadIdx.x;
    int beg = g_off[n], end = g_off[n + 1];
    float num = 0.f, den = 0.f;
    for (int j = beg; j < end; j++) {
        int eid = g_eids[j];
        float x = g_ehat[(size_t)eid * 128 + d];
        float s = 1.f / (1.f + __expf(-x));
        num += s * g_Bh[src[eid] * 128 + d];
        den += s;
    }
    float t = g_Ah[n * 128 + d] + num / (den + EPS_AGG);
    g_t[n * 128 + d] = t;
    atomicAdd(&g_stats[d], t);
    atomicAdd(&g_stats[128 + d], t * t);
}

// ---------------- h += relu(bn(t)) ----------------
__global__ __launch_bounds__(256) void k_node_update()
{
    int i = blockIdx.x * 256 + threadIdx.x;   // over N*32 float4s
    int d4 = (i & 31) << 2;
    float4 sc = *(const float4*)(g_bn_scale + d4);
    float4 sh = *(const float4*)(g_bn_shift + d4);
    float4 x = ((const float4*)g_t)[i];
    float4 hv = ((const float4*)g_h)[i];
    hv.x += fmaxf(fmaf(x.x, sc.x, sh.x), 0.f);
    hv.y += fmaxf(fmaf(x.y, sc.y, sh.y), 0.f);
    hv.z += fmaxf(fmaf(x.z, sc.z, sh.z), 0.f);
    hv.w += fmaxf(fmaf(x.w, sc.w, sh.w), 0.f);
    ((float4*)g_h)[i] = hv;
}

// ---------------- decoder: out[e] = dec_w . [h[src], h[dst], e] + dec_b ----------------
__global__ __launch_bounds__(256) void k_dec(const float* __restrict__ dw,
                                             const float* __restrict__ db,
                                             const int* __restrict__ src,
                                             const int* __restrict__ dst,
                                             float* __restrict__ out)
{
    int w = (blockIdx.x * 256 + threadIdx.x) >> 5;
    if (w >= N_EDGES) return;
    int lane = threadIdx.x & 31;
    int s = src[w], d = dst[w];
    float4 w1 = *(const float4*)(dw + lane * 4);
    float4 w2 = *(const float4*)(dw + 128 + lane * 4);
    float4 w3 = *(const float4*)(dw + 256 + lane * 4);
    float4 hs = *(const float4*)(g_h + s * 128 + lane * 4);
    float4 hd = *(const float4*)(g_h + d * 128 + lane * 4);
    float4 ee = *(const float4*)(g_e + (size_t)w * 128 + lane * 4);
    float acc = w1.x * hs.x + w1.y * hs.y + w1.z * hs.z + w1.w * hs.w
              + w2.x * hd.x + w2.y * hd.y + w2.z * hd.z + w2.w * hd.w
              + w3.x * ee.x + w3.y * ee.y + w3.z * ee.z + w3.w * ee.w;
#pragma unroll
    for (int ofs = 16; ofs > 0; ofs >>= 1) acc += __shfl_down_sync(0xffffffffu, acc, ofs);
    if (lane == 0) out[w] = acc + db[0];
}

// ---------------- launcher ----------------
extern "C" void kernel_launch(void* const* d_in, const int* in_sizes, int n_in,
                              void* d_out, int out_size)
{
    const float* emb    = (const float*)d_in[0];
    const float* conv_w = (const float*)d_in[1];
    const float* conv_b = (const float*)d_in[2];
    const float* ee_w   = (const float*)d_in[3];
    const float* ee_b   = (const float*)d_in[4];
    const float* Aw     = (const float*)d_in[5];
    const float* Ab     = (const float*)d_in[6];
    const float* Bw     = (const float*)d_in[7];
    const float* Bb     = (const float*)d_in[8];
    const float* Cw     = (const float*)d_in[9];
    const float* Cb     = (const float*)d_in[10];
    const float* Dw     = (const float*)d_in[11];
    const float* Db     = (const float*)d_in[12];
    const float* Ew     = (const float*)d_in[13];
    const float* Eb     = (const float*)d_in[14];
    const float* bnh_g  = (const float*)d_in[15];
    const float* bnh_b  = (const float*)d_in[16];
    const float* bne_g  = (const float*)d_in[17];
    const float* bne_b  = (const float*)d_in[18];
    const float* dec_w  = (const float*)d_in[19];
    const float* dec_b  = (const float*)d_in[20];
    const float* sim    = (const float*)d_in[21];
    const float* length = (const float*)d_in[22];
    const int*   reads  = (const int*)d_in[23];
    const int*   src    = (const int*)d_in[24];
    const int*   dst    = (const int*)d_in[25];
    float* out = (float*)d_out;

    const int smemN = (128 * 132 + 128 * 68) * 4;             // 102400
    const int smemE = smemN + 2 * 64 * 4 + 2 * 128 * 4;       // 103936
    cudaFuncSetAttribute(k_node_gemm, cudaFuncAttributeMaxDynamicSharedMemorySize, smemN);
    cudaFuncSetAttribute(k_edge_pass1, cudaFuncAttributeMaxDynamicSharedMemorySize, smemE);

    k_wsum<<<40, 256>>>(emb, conv_w);
    k_seq<<<N_NODES / 4, 512>>>(reads, conv_b);
    k_edge_enc<<<N_EDGES / 32, 128>>>(sim, length, ee_w, ee_b);
    k_zero_stats<<<1, 256>>>();
    k_csr_zero<<<(N_NODES + 255) / 256, 256>>>();
    k_hist<<<N_EDGES / 256, 256>>>(dst);
    k_scan<<<1, 1024>>>();
    k_scatter<<<N_EDGES / 256, 256>>>(dst);

    const float invE = 1.f / (float)N_EDGES;
    const float invN = 1.f / (float)N_NODES;
    for (int i = 0; i < N_LAYERS; i++) {
        const int wo = i * DIM * DIM, bo = i * DIM;
        k_node_gemm<<<(N_NODES + 63) / 64, 256, smemN>>>(
            Aw + wo, Bw + wo, Dw + wo, Ew + wo,
            Ab + bo, Bb + bo, Db + bo, Eb + bo);
        k_edge_pass1<<<N_EDGES / 64, 256, smemE>>>(Cw + wo, Cb + bo, src, dst);
        k_bn_final<<<1, 128>>>(bne_g + bo, bne_b + bo, invE);
        k_edge_update<<<(N_EDGES * 32) / 256, 256>>>();
        k_aggregate<<<N_NODES, 128>>>(src);
        k_bn_final<<<1, 128>>>(bnh_g + bo, bnh_b + bo, invN);
        k_node_update<<<(N_NODES * 32) / 256, 256>>>();
    }
    k_dec<<<(N_EDGES * 32 + 255) / 256, 256>>>(dec_w, dec_b, src, dst, out);
}

// round 3
// speedup vs baseline: 1.0694x; 1.0694x over previous
#include <cuda_runtime.h>
#include <cuda_bf16.h>
#include <cstdint>

#define N_NODES 20000
#define READ_LEN 64
#define N_EDGES 320000
#define DIM 128
#define KSZ 20
#define CONV_T (READ_LEN - KSZ + 1)
#define N_LAYERS 4
#define EPS_BN 1e-5f
#define EPS_AGG 1e-6f

typedef unsigned long long ull;

// packed fp32x2 FMA (Blackwell): d = a*b + d elementwise on packed pairs
#define FMA2(d, a, b) asm("fma.rn.f32x2 %0, %1, %2, %0;" : "+l"(d) : "l"(a), "l"(b))
#define PACK2(d, x)   asm("mov.b64 %0, {%1, %1};" : "=l"(d) : "f"(x))
#define UNPACK2(lo, hi, p) asm("mov.b64 {%0, %1}, %2;" : "=f"(lo), "=f"(hi) : "l"(p))

// ---------------- device scratch (no allocations allowed) ----------------
__device__ float g_h[N_NODES * DIM];
__device__ float g_e[(size_t)N_EDGES * DIM];
__device__ float g_ehat[(size_t)N_EDGES * DIM];
__device__ float g_Ah[N_NODES * DIM];
__device__ float g_Bh[N_NODES * DIM];
__device__ float g_Dh[N_NODES * DIM];
__device__ float g_Eh[N_NODES * DIM];
__device__ float g_t[N_NODES * DIM];
__device__ float g_wsum[4 * KSZ * DIM];
__device__ float g_W2[10 * 16 * DIM];     // pair table: [k2][c2][d]
__device__ float g_stats[2 * DIM];        // zero-init; invariant: zero between runs
__device__ float g_bn_scale[DIM];
__device__ float g_bn_shift[DIM];
__device__ int g_cnt[N_NODES];
__device__ int g_off[N_NODES + 1];
__device__ int g_cur[N_NODES];
__device__ int g_eids[N_EDGES];

// ---------------- sequence encoder ----------------
// wsum[b][k][d] = sum_c emb[b][c] * conv_w[d][c][k]
__global__ void k_wsum(const float* __restrict__ emb, const float* __restrict__ cw)
{
    int idx = blockIdx.x * 256 + threadIdx.x;
    if (idx >= 4 * KSZ * DIM) return;
    int d = idx & 127;
    int bk = idx >> 7;
    int k = bk % KSZ, b = bk / KSZ;
    float s = 0.f;
#pragma unroll
    for (int c = 0; c < 3; c++) s += emb[b * 3 + c] * cw[d * 3 * KSZ + c * KSZ + k];
    g_wsum[idx] = s;
}

// pair table: W2[(k2*16 + a*4 + b)*128 + d] = wsum[a][2k2][d] + wsum[b][2k2+1][d]
__global__ void k_W2()
{
    int idx = blockIdx.x * 256 + threadIdx.x;
    if (idx >= 10 * 16 * DIM) return;
    int d = idx & 127;
    int r = idx >> 7;
    int c2 = r & 15, k2 = r >> 4;
    int a = c2 >> 2, b = c2 & 3;
    g_W2[idx] = g_wsum[(a * KSZ + 2 * k2) * DIM + d] + g_wsum[(b * KSZ + 2 * k2 + 1) * DIM + d];
}

// 8 nodes per block; each thread handles one node x d-pair.
__global__ __launch_bounds__(512) void k_seq(const int* __restrict__ reads,
                                             const float* __restrict__ conv_b)
{
    extern __shared__ float sm[];
    float* sW2 = sm;                       // 10*16*128 floats = 80KB
    int* scode = (int*)(sm + 10 * 16 * DIM);  // 512 ints
    int* spc = scode + 512;                   // 512 ints (pc*128)
    int tid = threadIdx.x;

    for (int i = tid; i < (10 * 16 * DIM) / 4; i += 512)
        ((float4*)sW2)[i] = ((const float4*)g_W2)[i];

    int nl = tid >> 6, l = tid & 63;
    int n = blockIdx.x * 8 + nl;
    scode[tid] = reads[n * READ_LEN + l];
    __syncthreads();
    if (l < 63) spc[tid] = (scode[tid] * 4 + scode[tid + 1]) << 7;
    __syncthreads();

    int dp = tid & 63;
    const float* wd = sW2 + dp * 2;
    const int* pc = spc + nl * 64;
    float m0 = -3.4e38f, m1 = -3.4e38f;
#pragma unroll
    for (int t = 0; t < CONV_T; t++) {
        float s0 = 0.f, s1 = 0.f;
#pragma unroll
        for (int k2 = 0; k2 < 10; k2++) {
            float2 v = *(const float2*)(wd + pc[t + 2 * k2] + k2 * 2048);
            s0 += v.x; s1 += v.y;
        }
        m0 = fmaxf(m0, s0);
        m1 = fmaxf(m1, s1);
    }
    float2 bv = *(const float2*)(conv_b + dp * 2);
    float2 hv;
    hv.x = fmaxf(m0 + bv.x, 0.f);
    hv.y = fmaxf(m1 + bv.y, 0.f);
    *(float2*)(g_h + n * DIM + dp * 2) = hv;
}

// ---------------- edge encoder ----------------
__global__ __launch_bounds__(128) void k_edge_enc(const float* __restrict__ sim,
                                                  const float* __restrict__ len,
                                                  const float* __restrict__ ew,
                                                  const float* __restrict__ eb)
{
    int d = threadIdx.x;
    float w0 = ew[d * 2], w1 = ew[d * 2 + 1], b = eb[d];
    int e0 = blockIdx.x * 32;
#pragma unroll 4
    for (int j = 0; j < 32; j++) {
        int eid = e0 + j;
        g_e[(size_t)eid * DIM + d] = fmaf(sim[eid], w0, fmaf(len[eid], w1, b));
    }
}

// ---------------- CSR build by dst ----------------
__global__ void k_csr_zero()
{
    int i = blockIdx.x * 256 + threadIdx.x;
    if (i < N_NODES) g_cnt[i] = 0;
}
__global__ void k_hist(const int* __restrict__ dst)
{
    int i = blockIdx.x * 256 + threadIdx.x;
    if (i < N_EDGES) atomicAdd(&g_cnt[dst[i]], 1);
}
__global__ __launch_bounds__(1024) void k_scan()
{
    __shared__ int sd[1024];
    int tid = threadIdx.x;
    int carry = 0;
    for (int base = 0; base < N_NODES; base += 1024) {
        int i = base + tid;
        int v = (i < N_NODES) ? g_cnt[i] : 0;
        __syncthreads();
        sd[tid] = v;
        __syncthreads();
        for (int ofs = 1; ofs < 1024; ofs <<= 1) {
            int t = (tid >= ofs) ? sd[tid - ofs] : 0;
            __syncthreads();
            sd[tid] += t;
            __syncthreads();
        }
        if (i < N_NODES) {
            int ex = carry + sd[tid] - v;
            g_off[i] = ex;
            g_cur[i] = ex;
        }
        carry += sd[1023];
    }
    if (tid == 0) g_off[N_NODES] = carry;
}
__global__ void k_scatter(const int* __restrict__ dst)
{
    int i = blockIdx.x * 256 + threadIdx.x;
    if (i < N_EDGES) {
        int p = atomicAdd(&g_cur[dst[i]], 1);
        g_eids[p] = i;
    }
}

// ---------------- BN finalize (also restores g_stats zero invariant) ----------------
__global__ __launch_bounds__(128) void k_bn_final(const float* __restrict__ g,
                                                  const float* __restrict__ b,
                                                  float invc)
{
    int d = threadIdx.x;
    float s = g_stats[d], sq = g_stats[128 + d];
    float mean = s * invc;
    float var = sq * invc - mean * mean;
    float sc = g[d] * rsqrtf(var + EPS_BN);
    g_bn_scale[d] = sc;
    g_bn_shift[d] = b[d] - mean * sc;
    g_stats[d] = 0.f;
    g_stats[128 + d] = 0.f;
}

// ---------------- node GEMM: Ah,Bh,Dh,Eh = h @ W.T + bias ----------------
__global__ __launch_bounds__(256, 2) void k_node_gemm(
    const float* __restrict__ Wa, const float* __restrict__ Wb,
    const float* __restrict__ Wd, const float* __restrict__ We,
    const float* __restrict__ Ba, const float* __restrict__ Bb_,
    const float* __restrict__ Bd, const float* __restrict__ Be)
{
    const float* Wp[4] = {Wa, Wb, Wd, We};
    const float* Bp[4] = {Ba, Bb_, Bd, Be};
    float* Op[4] = {g_Ah, g_Bh, g_Dh, g_Eh};
    extern __shared__ float sm[];
    float* Ws = sm;               // [128][132]
    float* Hs = sm + 128 * 132;   // [128][68]
    int tid = threadIdx.x;
    int n0 = blockIdx.x * 64;
    int mlim = N_NODES - n0;
    if (mlim > 64) mlim = 64;

    for (int i = tid; i < 64 * 128; i += 256) {
        int m = i >> 7, k = i & 127;
        Hs[k * 68 + m] = (m < mlim) ? g_h[(n0 + m) * 128 + k] : 0.f;
    }
    int tx = tid & 31, ty = tid >> 5;
    const float* Erow = Hs + (ty << 3);
    const float* Wrow = Ws + (tx << 2);

    for (int mat = 0; mat < 4; mat++) {
        __syncthreads();
        const float* W = Wp[mat];
        for (int i = tid; i < 128 * 128; i += 256) {
            int d = i >> 7, k = i & 127;
            Ws[k * 132 + d] = W[i];
        }
        __syncthreads();
        ull acc[16];
#pragma unroll
        for (int i = 0; i < 16; i++) acc[i] = 0ull;
#pragma unroll 4
        for (int k = 0; k < 128; k++) {
            ulonglong2 a01 = *(const ulonglong2*)(Erow + k * 68);
            ulonglong2 a23 = *(const ulonglong2*)(Erow + k * 68 + 4);
            float4 w4 = *(const float4*)(Wrow + k * 132);
            ull b0, b1, b2, b3;
            PACK2(b0, w4.x); PACK2(b1, w4.y); PACK2(b2, w4.z); PACK2(b3, w4.w);
            FMA2(acc[0], a01.x, b0); FMA2(acc[1], a01.x, b1);
            FMA2(acc[2], a01.x, b2); FMA2(acc[3], a01.x, b3);
            FMA2(acc[4], a01.y, b0); FMA2(acc[5], a01.y, b1);
            FMA2(acc[6], a01.y, b2); FMA2(acc[7], a01.y, b3);
            FMA2(acc[8], a23.x, b0); FMA2(acc[9], a23.x, b1);
            FMA2(acc[10], a23.x, b2); FMA2(acc[11], a23.x, b3);
            FMA2(acc[12], a23.y, b0); FMA2(acc[13], a23.y, b1);
            FMA2(acc[14], a23.y, b2); FMA2(acc[15], a23.y, b3);
        }
        float4 bias = *(const float4*)(Bp[mat] + (tx << 2));
        float* Out = Op[mat];
#pragma unroll
        for (int mp = 0; mp < 4; mp++) {
            float lo0, hi0, lo1, hi1, lo2, hi2, lo3, hi3;
            UNPACK2(lo0, hi0, acc[mp * 4 + 0]);
            UNPACK2(lo1, hi1, acc[mp * 4 + 1]);
            UNPACK2(lo2, hi2, acc[mp * 4 + 2]);
            UNPACK2(lo3, hi3, acc[mp * 4 + 3]);
            int ml = (ty << 3) + mp * 2;
            if (ml < mlim) {
                float4 v = {lo0 + bias.x, lo1 + bias.y, lo2 + bias.z, lo3 + bias.w};
                *(float4*)(Out + (n0 + ml) * 128 + (tx << 2)) = v;
            }
            if (ml + 1 < mlim) {
                float4 v = {hi0 + bias.x, hi1 + bias.y, hi2 + bias.z, hi3 + bias.w};
                *(float4*)(Out + (n0 + ml + 1) * 128 + (tx << 2)) = v;
            }
        }
    }
}

// ---------------- edge pass1: ehat = e @ Cw.T + Cb + Dh[dst] + Eh[src]; BN stats ----------------
__global__ __launch_bounds__(256, 2) void k_edge_pass1(const float* __restrict__ Cw,
                                                       const float* __restrict__ Cb,
                                                       const int* __restrict__ src,
                                                       const int* __restrict__ dst)
{
    extern __shared__ float sm[];
    float* Ws = sm;               // [128][132]
    float* Es = sm + 128 * 132;   // [128][68]
    int* s_src = (int*)(Es + 128 * 68);
    int* s_dst = s_src + 64;
    float* ssum = (float*)(s_dst + 64);
    float* ssq = ssum + 128;
    int tid = threadIdx.x;
    int e0 = blockIdx.x * 64;

    for (int i = tid; i < 128 * 128; i += 256) {
        int d = i >> 7, k = i & 127;
        Ws[k * 132 + d] = Cw[i];
    }
    for (int i = tid; i < 64 * 128; i += 256) {
        int m = i >> 7, k = i & 127;
        Es[k * 68 + m] = g_e[(size_t)(e0 + m) * 128 + k];
    }
    if (tid < 64) { s_src[tid] = src[e0 + tid]; s_dst[tid] = dst[e0 + tid]; }
    if (tid < 128) { ssum[tid] = 0.f; ssq[tid] = 0.f; }
    __syncthreads();

    int tx = tid & 31, ty = tid >> 5;
    const float* Erow = Es + (ty << 3);
    const float* Wrow = Ws + (tx << 2);
    ull acc[16];
#pragma unroll
    for (int i = 0; i < 16; i++) acc[i] = 0ull;
#pragma unroll 4
    for (int k = 0; k < 128; k++) {
        ulonglong2 a01 = *(const ulonglong2*)(Erow + k * 68);
        ulonglong2 a23 = *(const ulonglong2*)(Erow + k * 68 + 4);
        float4 w4 = *(const float4*)(Wrow + k * 132);
        ull b0, b1, b2, b3;
        PACK2(b0, w4.x); PACK2(b1, w4.y); PACK2(b2, w4.z); PACK2(b3, w4.w);
        FMA2(acc[0], a01.x, b0); FMA2(acc[1], a01.x, b1);
        FMA2(acc[2], a01.x, b2); FMA2(acc[3], a01.x, b3);
        FMA2(acc[4], a01.y, b0); FMA2(acc[5], a01.y, b1);
        FMA2(acc[6], a01.y, b2); FMA2(acc[7], a01.y, b3);
        FMA2(acc[8], a23.x, b0); FMA2(acc[9], a23.x, b1);
        FMA2(acc[10], a23.x, b2); FMA2(acc[11], a23.x, b3);
        FMA2(acc[12], a23.y, b0); FMA2(acc[13], a23.y, b1);
        FMA2(acc[14], a23.y, b2); FMA2(acc[15], a23.y, b3);
    }

    float4 cb = *(const float4*)(Cb + (tx << 2));
    float ls0 = 0.f, ls1 = 0.f, ls2 = 0.f, ls3 = 0.f;
    float lq0 = 0.f, lq1 = 0.f, lq2 = 0.f, lq3 = 0.f;
#pragma unroll
    for (int mp = 0; mp < 4; mp++) {
        float lo0, hi0, lo1, hi1, lo2, hi2, lo3, hi3;
        UNPACK2(lo0, hi0, acc[mp * 4 + 0]);
        UNPACK2(lo1, hi1, acc[mp * 4 + 1]);
        UNPACK2(lo2, hi2, acc[mp * 4 + 2]);
        UNPACK2(lo3, hi3, acc[mp * 4 + 3]);
#pragma unroll
        for (int half = 0; half < 2; half++) {
            int ml = (ty << 3) + mp * 2 + half;
            float v0 = half ? hi0 : lo0, v1 = half ? hi1 : lo1;
            float v2 = half ? hi2 : lo2, v3 = half ? hi3 : lo3;
            int sr = s_src[ml], dd = s_dst[ml];
            float4 dh = *(const float4*)(g_Dh + dd * 128 + (tx << 2));
            float4 eh = *(const float4*)(g_Eh + sr * 128 + (tx << 2));
            float4 v;
            v.x = v0 + cb.x + dh.x + eh.x;
            v.y = v1 + cb.y + dh.y + eh.y;
            v.z = v2 + cb.z + dh.z + eh.z;
            v.w = v3 + cb.w + dh.w + eh.w;
            *(float4*)(g_ehat + (size_t)(e0 + ml) * 128 + (tx << 2)) = v;
            ls0 += v.x; lq0 += v.x * v.x;
            ls1 += v.y; lq1 += v.y * v.y;
            ls2 += v.z; lq2 += v.z * v.z;
            ls3 += v.w; lq3 += v.w * v.w;
        }
    }
    int d0 = tx << 2;
    atomicAdd(&ssum[d0 + 0], ls0); atomicAdd(&ssq[d0 + 0], lq0);
    atomicAdd(&ssum[d0 + 1], ls1); atomicAdd(&ssq[d0 + 1], lq1);
    atomicAdd(&ssum[d0 + 2], ls2); atomicAdd(&ssq[d0 + 2], lq2);
    atomicAdd(&ssum[d0 + 3], ls3); atomicAdd(&ssq[d0 + 3], lq3);
    __syncthreads();
    if (tid < 128) {
        atomicAdd(&g_stats[tid], ssum[tid]);
        atomicAdd(&g_stats[128 + tid], ssq[tid]);
    }
}

// ---------------- e += relu(bn(ehat)) ----------------
__global__ __launch_bounds__(256) void k_edge_update()
{
    int i = blockIdx.x * 256 + threadIdx.x;   // over E*32 float4s
    int d4 = (i & 31) << 2;
    float4 sc = *(const float4*)(g_bn_scale + d4);
    float4 sh = *(const float4*)(g_bn_shift + d4);
    float4 x = ((const float4*)g_ehat)[i];
    float4 ev = ((const float4*)g_e)[i];
    ev.x += fmaxf(fmaf(x.x, sc.x, sh.x), 0.f);
    ev.y += fmaxf(fmaf(x.y, sc.y, sh.y), 0.f);
    ev.z += fmaxf(fmaf(x.z, sc.z, sh.z), 0.f);
    ev.w += fmaxf(fmaf(x.w, sc.w, sh.w), 0.f);
    ((float4*)g_e)[i] = ev;
}

// ---------------- aggregation: t = Ah + segsum(sigma*Bh[src]) / (segsum(sigma)+eps) ----------------
__global__ __launch_bounds__(128) void k_aggregate(const int* __restrict__ src)
{
    int n = blockIdx.x;
    int d = threadIdx.x;
    int beg = g_off[n], end = g_off[n + 1];
    float num = 0.f, den = 0.f;
    for (int j = beg; j < end; j++) {
        int eid = g_eids[j];
        float x = g_ehat[(size_t)eid * 128 + d];
        float s = 1.f / (1.f + __expf(-x));
        num += s * g_Bh[src[eid] * 128 + d];
        den += s;
    }
    float t = g_Ah[n * 128 + d] + num / (den + EPS_AGG);
    g_t[n * 128 + d] = t;
    atomicAdd(&g_stats[d], t);
    atomicAdd(&g_stats[128 + d], t * t);
}

// ---------------- h += relu(bn(t)) ----------------
__global__ __launch_bounds__(256) void k_node_update()
{
    int i = blockIdx.x * 256 + threadIdx.x;   // over N*32 float4s
    int d4 = (i & 31) << 2;
    float4 sc = *(const float4*)(g_bn_scale + d4);
    float4 sh = *(const float4*)(g_bn_shift + d4);
    float4 x = ((const float4*)g_t)[i];
    float4 hv = ((const float4*)g_h)[i];
    hv.x += fmaxf(fmaf(x.x, sc.x, sh.x), 0.f);
    hv.y += fmaxf(fmaf(x.y, sc.y, sh.y), 0.f);
    hv.z += fmaxf(fmaf(x.z, sc.z, sh.z), 0.f);
    hv.w += fmaxf(fmaf(x.w, sc.w, sh.w), 0.f);
    ((float4*)g_h)[i] = hv;
}

// ---------------- decoder ----------------
__global__ __launch_bounds__(256) void k_dec(const float* __restrict__ dw,
                                             const float* __restrict__ db,
                                             const int* __restrict__ src,
                                             const int* __restrict__ dst,
                                             float* __restrict__ out)
{
    int w = (blockIdx.x * 256 + threadIdx.x) >> 5;
    if (w >= N_EDGES) return;
    int lane = threadIdx.x & 31;
    int s = src[w], d = dst[w];
    float4 w1 = *(const float4*)(dw + lane * 4);
    float4 w2 = *(const float4*)(dw + 128 + lane * 4);
    float4 w3 = *(const float4*)(dw + 256 + lane * 4);
    float4 hs = *(const float4*)(g_h + s * 128 + lane * 4);
    float4 hd = *(const float4*)(g_h + d * 128 + lane * 4);
    float4 ee = *(const float4*)(g_e + (size_t)w * 128 + lane * 4);
    float acc = w1.x * hs.x + w1.y * hs.y + w1.z * hs.z + w1.w * hs.w
              + w2.x * hd.x + w2.y * hd.y + w2.z * hd.z + w2.w * hd.w
              + w3.x * ee.x + w3.y * ee.y + w3.z * ee.z + w3.w * ee.w;
#pragma unroll
    for (int ofs = 16; ofs > 0; ofs >>= 1) acc += __shfl_down_sync(0xffffffffu, acc, ofs);
    if (lane == 0) out[w] = acc + db[0];
}

// ---------------- launcher ----------------
extern "C" void kernel_launch(void* const* d_in, const int* in_sizes, int n_in,
                              void* d_out, int out_size)
{
    const float* emb    = (const float*)d_in[0];
    const float* conv_w = (const float*)d_in[1];
    const float* conv_b = (const float*)d_in[2];
    const float* ee_w   = (const float*)d_in[3];
    const float* ee_b   = (const float*)d_in[4];
    const float* Aw     = (const float*)d_in[5];
    const float* Ab     = (const float*)d_in[6];
    const float* Bw     = (const float*)d_in[7];
    const float* Bb     = (const float*)d_in[8];
    const float* Cw     = (const float*)d_in[9];
    const float* Cb     = (const float*)d_in[10];
    const float* Dw     = (const float*)d_in[11];
    const float* Db     = (const float*)d_in[12];
    const float* Ew     = (const float*)d_in[13];
    const float* Eb     = (const float*)d_in[14];
    const float* bnh_g  = (const float*)d_in[15];
    const float* bnh_b  = (const float*)d_in[16];
    const float* bne_g  = (const float*)d_in[17];
    const float* bne_b  = (const float*)d_in[18];
    const float* dec_w  = (const float*)d_in[19];
    const float* dec_b  = (const float*)d_in[20];
    const float* sim    = (const float*)d_in[21];
    const float* length = (const float*)d_in[22];
    const int*   reads  = (const int*)d_in[23];
    const int*   src    = (const int*)d_in[24];
    const int*   dst    = (const int*)d_in[25];
    float* out = (float*)d_out;

    const int smemN = (128 * 132 + 128 * 68) * 4;             // 102400
    const int smemE = smemN + 2 * 64 * 4 + 2 * 128 * 4;       // 103936
    const int smemS = (10 * 16 * DIM) * 4 + 2 * 512 * 4;      // 86016
    cudaFuncSetAttribute(k_node_gemm, cudaFuncAttributeMaxDynamicSharedMemorySize, smemN);
    cudaFuncSetAttribute(k_edge_pass1, cudaFuncAttributeMaxDynamicSharedMemorySize, smemE);
    cudaFuncSetAttribute(k_seq, cudaFuncAttributeMaxDynamicSharedMemorySize, smemS);

    const float invE = 1.f / (float)N_EDGES;
    const float invN = 1.f / (float)N_NODES;

    // launches 0..5 ordered so ncu (-s 5 -c 1) profiles k_edge_pass1
    k_wsum<<<40, 256>>>(emb, conv_w);                                   // 0
    k_W2<<<(10 * 16 * DIM + 255) / 256, 256>>>();                       // 1
    k_seq<<<N_NODES / 8, 512, smemS>>>(reads, conv_b);                  // 2
    k_edge_enc<<<N_EDGES / 32, 128>>>(sim, length, ee_w, ee_b);         // 3
    k_node_gemm<<<(N_NODES + 63) / 64, 256, smemN>>>(                   // 4
        Aw, Bw, Dw, Ew, Ab, Bb, Db, Eb);
    k_edge_pass1<<<N_EDGES / 64, 256, smemE>>>(Cw, Cb, src, dst);       // 5  <- profiled

    // CSR build (independent; needed before first k_aggregate)
    k_csr_zero<<<(N_NODES + 255) / 256, 256>>>();
    k_hist<<<N_EDGES / 256, 256>>>(dst);
    k_scan<<<1, 1024>>>();
    k_scatter<<<N_EDGES / 256, 256>>>(dst);

    // finish layer 0
    k_bn_final<<<1, 128>>>(bne_g, bne_b, invE);
    k_edge_update<<<(N_EDGES * 32) / 256, 256>>>();
    k_aggregate<<<N_NODES, 128>>>(src);
    k_bn_final<<<1, 128>>>(bnh_g, bnh_b, invN);
    k_node_update<<<(N_NODES * 32) / 256, 256>>>();

    for (int i = 1; i < N_LAYERS; i++) {
        const int wo = i * DIM * DIM, bo = i * DIM;
        k_node_gemm<<<(N_NODES + 63) / 64, 256, smemN>>>(
            Aw + wo, Bw + wo, Dw + wo, Ew + wo,
            Ab + bo, Bb + bo, Db + bo, Eb + bo);
        k_edge_pass1<<<N_EDGES / 64, 256, smemE>>>(Cw + wo, Cb + bo, src, dst);
        k_bn_final<<<1, 128>>>(bne_g + bo, bne_b + bo, invE);
        k_edge_update<<<(N_EDGES * 32) / 256, 256>>>();
        k_aggregate<<<N_NODES, 128>>>(src);
        k_bn_final<<<1, 128>>>(bnh_g + bo, bnh_b + bo, invN);
        k_node_update<<<(N_NODES * 32) / 256, 256>>>();
    }
    k_dec<<<(N_EDGES * 32 + 255) / 256, 256>>>(dec_w, dec_b, src, dst, out);
}

// round 4
// speedup vs baseline: 1.0804x; 1.0103x over previous
#include <cuda_runtime.h>
#include <cuda_bf16.h>
#include <cstdint>

#define N_NODES 20000
#define READ_LEN 64
#define N_EDGES 320000
#define DIM 128
#define KSZ 20
#define CONV_T (READ_LEN - KSZ + 1)
#define N_LAYERS 4
#define EPS_BN 1e-5f
#define EPS_AGG 1e-6f

typedef __nv_bfloat16 bf16;
typedef unsigned long long ull;

#define SBF 136   // bf16 smem row stride (272B: ldmatrix ~conflict-light)
#define SCF 132   // fp32 C smem row stride

// ---------------- device scratch ----------------
__device__ float g_h[N_NODES * DIM];
__device__ float g_e[(size_t)N_EDGES * DIM];
__device__ float g_ehat[(size_t)N_EDGES * DIM];
__device__ float g_Ah[N_NODES * DIM];
__device__ float g_Bh[N_NODES * DIM];
__device__ float g_Dh[N_NODES * DIM];
__device__ float g_Eh[N_NODES * DIM];
__device__ float g_t[N_NODES * DIM];
__device__ float g_wsum[4 * KSZ * DIM];
__device__ float g_W2[10 * 16 * DIM];
__device__ float g_stats[2 * DIM];        // zero-init; bn_final restores zeros
__device__ float g_bn_scale[DIM];
__device__ float g_bn_shift[DIM];
__device__ int g_cnt[N_NODES];
__device__ int g_off[N_NODES + 1];
__device__ int g_cur[N_NODES];
__device__ int g_eids[N_EDGES];

// ---------------- mma helpers ----------------
__device__ __forceinline__ unsigned s2u(const void* p)
{
    return (unsigned)__cvta_generic_to_shared(p);
}
__device__ __forceinline__ void ldsm4(unsigned* r, unsigned addr)
{
    asm volatile("ldmatrix.sync.aligned.m8n8.x4.shared.b16 {%0,%1,%2,%3}, [%4];"
                 : "=r"(r[0]), "=r"(r[1]), "=r"(r[2]), "=r"(r[3]) : "r"(addr));
}
__device__ __forceinline__ void mma16816(float* c, const unsigned* a, const unsigned* b)
{
    asm volatile("mma.sync.aligned.m16n8k16.row.col.f32.bf16.bf16.f32 "
                 "{%0,%1,%2,%3}, {%4,%5,%6,%7}, {%8,%9}, {%0,%1,%2,%3};"
                 : "+f"(c[0]), "+f"(c[1]), "+f"(c[2]), "+f"(c[3])
                 : "r"(a[0]), "r"(a[1]), "r"(a[2]), "r"(a[3]), "r"(b[0]), "r"(b[1]));
}
__device__ __forceinline__ unsigned pb2(float a, float b)
{
    __nv_bfloat162 t = __floats2bfloat162_rn(a, b);
    return *(unsigned*)&t;
}

// split fp32 tile [rows<=128][128] (row stride 128) into hi/lo bf16 smem tiles
__device__ __forceinline__ void split_tile(const float* __restrict__ g, int rows,
                                           bf16* hi, bf16* lo, int tid)
{
    for (int i = tid; i < 128 * 32; i += 256) {
        int r = i >> 5, c = (i & 31) << 2;
        float4 v = make_float4(0.f, 0.f, 0.f, 0.f);
        if (r < rows) v = *(const float4*)(g + r * 128 + c);
        float hx = __bfloat162float(__float2bfloat16(v.x));
        float hy = __bfloat162float(__float2bfloat16(v.y));
        float hz = __bfloat162float(__float2bfloat16(v.z));
        float hw = __bfloat162float(__float2bfloat16(v.w));
        uint2 hp = make_uint2(pb2(hx, hy), pb2(hz, hw));
        uint2 lp = make_uint2(pb2(v.x - hx, v.y - hy), pb2(v.z - hz, v.w - hw));
        *(uint2*)(hi + r * SBF + c) = hp;
        *(uint2*)(lo + r * SBF + c) = lp;
    }
}

// mainloop: acc[2][8][4] += (Ahi Bhi + Ahi Blo + Alo Bhi) for this block tile
__device__ __forceinline__ void mma_mainloop(const bf16* ahi, const bf16* alo,
                                             const bf16* whi, const bf16* wlo,
                                             int m0w, int n0w, int lane,
                                             float acc[2][8][4])
{
    int aoff = (lane & 15) * SBF + (lane >> 4) * 8;
    int boff = ((lane & 7) + ((lane >> 4) << 3)) * SBF + ((lane >> 3) & 1) * 8;
#pragma unroll
    for (int kt = 0; kt < 8; kt++) {
        unsigned af[2][2][4], bf[2][4][4];
#pragma unroll
        for (int ms = 0; ms < 2; ms++) {
            int o = (m0w + ms * 16) * SBF + aoff + kt * 16;
            ldsm4(af[0][ms], s2u(ahi + o));
            ldsm4(af[1][ms], s2u(alo + o));
        }
#pragma unroll
        for (int np = 0; np < 4; np++) {
            int o = (n0w + np * 16) * SBF + boff + kt * 16;
            ldsm4(bf[0][np], s2u(whi + o));
            ldsm4(bf[1][np], s2u(wlo + o));
        }
#pragma unroll
        for (int ms = 0; ms < 2; ms++)
#pragma unroll
            for (int nt = 0; nt < 8; nt++)
                mma16816(acc[ms][nt], af[0][ms], &bf[0][nt >> 1][(nt & 1) * 2]);
#pragma unroll
        for (int ms = 0; ms < 2; ms++)
#pragma unroll
            for (int nt = 0; nt < 8; nt++)
                mma16816(acc[ms][nt], af[0][ms], &bf[1][nt >> 1][(nt & 1) * 2]);
#pragma unroll
        for (int ms = 0; ms < 2; ms++)
#pragma unroll
            for (int nt = 0; nt < 8; nt++)
                mma16816(acc[ms][nt], af[1][ms], &bf[0][nt >> 1][(nt & 1) * 2]);
    }
}

// ---------------- sequence encoder ----------------
__global__ void k_wsum(const float* __restrict__ emb, const float* __restrict__ cw)
{
    int idx = blockIdx.x * 256 + threadIdx.x;
    if (idx >= 4 * KSZ * DIM) return;
    int d = idx & 127;
    int bk = idx >> 7;
    int k = bk % KSZ, b = bk / KSZ;
    float s = 0.f;
#pragma unroll
    for (int c = 0; c < 3; c++) s += emb[b * 3 + c] * cw[d * 3 * KSZ + c * KSZ + k];
    g_wsum[idx] = s;
}

__global__ void k_W2()
{
    int idx = blockIdx.x * 256 + threadIdx.x;
    if (idx >= 10 * 16 * DIM) return;
    int d = idx & 127;
    int r = idx >> 7;
    int c2 = r & 15, k2 = r >> 4;
    int a = c2 >> 2, b = c2 & 3;
    g_W2[idx] = g_wsum[(a * KSZ + 2 * k2) * DIM + d] + g_wsum[(b * KSZ + 2 * k2 + 1) * DIM + d];
}

__global__ __launch_bounds__(512) void k_seq(const int* __restrict__ reads,
                                             const float* __restrict__ conv_b)
{
    extern __shared__ float sm[];
    float* sW2 = sm;
    int* scode = (int*)(sm + 10 * 16 * DIM);
    int* spc = scode + 512;
    int tid = threadIdx.x;

    for (int i = tid; i < (10 * 16 * DIM) / 4; i += 512)
        ((float4*)sW2)[i] = ((const float4*)g_W2)[i];

    int nl = tid >> 6, l = tid & 63;
    int n = blockIdx.x * 8 + nl;
    scode[tid] = reads[n * READ_LEN + l];
    __syncthreads();
    if (l < 63) spc[tid] = (scode[tid] * 4 + scode[tid + 1]) << 7;
    __syncthreads();

    int dp = tid & 63;
    const float* wd = sW2 + dp * 2;
    const int* pc = spc + nl * 64;
    float m0 = -3.4e38f, m1 = -3.4e38f;
#pragma unroll
    for (int t = 0; t < CONV_T; t++) {
        float s0 = 0.f, s1 = 0.f;
#pragma unroll
        for (int k2 = 0; k2 < 10; k2++) {
            float2 v = *(const float2*)(wd + pc[t + 2 * k2] + k2 * 2048);
            s0 += v.x; s1 += v.y;
        }
        m0 = fmaxf(m0, s0);
        m1 = fmaxf(m1, s1);
    }
    float2 bv = *(const float2*)(conv_b + dp * 2);
    float2 hv;
    hv.x = fmaxf(m0 + bv.x, 0.f);
    hv.y = fmaxf(m1 + bv.y, 0.f);
    *(float2*)(g_h + n * DIM + dp * 2) = hv;
}

// ---------------- edge encoder ----------------
__global__ __launch_bounds__(128) void k_edge_enc(const float* __restrict__ sim,
                                                  const float* __restrict__ len,
                                                  const float* __restrict__ ew,
                                                  const float* __restrict__ eb)
{
    int d = threadIdx.x;
    float w0 = ew[d * 2], w1 = ew[d * 2 + 1], b = eb[d];
    int e0 = blockIdx.x * 32;
#pragma unroll 4
    for (int j = 0; j < 32; j++) {
        int eid = e0 + j;
        g_e[(size_t)eid * DIM + d] = fmaf(sim[eid], w0, fmaf(len[eid], w1, b));
    }
}

// ---------------- CSR build by dst ----------------
__global__ void k_csr_zero()
{
    int i = blockIdx.x * 256 + threadIdx.x;
    if (i < N_NODES) g_cnt[i] = 0;
}
__global__ void k_hist(const int* __restrict__ dst)
{
    int i = blockIdx.x * 256 + threadIdx.x;
    if (i < N_EDGES) atomicAdd(&g_cnt[dst[i]], 1);
}
__global__ __launch_bounds__(1024) void k_scan()
{
    __shared__ int sd[1024];
    int tid = threadIdx.x;
    int carry = 0;
    for (int base = 0; base < N_NODES; base += 1024) {
        int i = base + tid;
        int v = (i < N_NODES) ? g_cnt[i] : 0;
        __syncthreads();
        sd[tid] = v;
        __syncthreads();
        for (int ofs = 1; ofs < 1024; ofs <<= 1) {
            int t = (tid >= ofs) ? sd[tid - ofs] : 0;
            __syncthreads();
            sd[tid] += t;
            __syncthreads();
        }
        if (i < N_NODES) {
            int ex = carry + sd[tid] - v;
            g_off[i] = ex;
            g_cur[i] = ex;
        }
        carry += sd[1023];
    }
    if (tid == 0) g_off[N_NODES] = carry;
}
__global__ void k_scatter(const int* __restrict__ dst)
{
    int i = blockIdx.x * 256 + threadIdx.x;
    if (i < N_EDGES) {
        int p = atomicAdd(&g_cur[dst[i]], 1);
        g_eids[p] = i;
    }
}

// ---------------- BN finalize (restores g_stats zero invariant) ----------------
__global__ __launch_bounds__(128) void k_bn_final(const float* __restrict__ g,
                                                  const float* __restrict__ b,
                                                  float invc)
{
    int d = threadIdx.x;
    float s = g_stats[d], sq = g_stats[128 + d];
    float mean = s * invc;
    float var = sq * invc - mean * mean;
    float sc = g[d] * rsqrtf(var + EPS_BN);
    g_bn_scale[d] = sc;
    g_bn_shift[d] = b[d] - mean * sc;
    g_stats[d] = 0.f;
    g_stats[128 + d] = 0.f;
}

// ---------------- node GEMM (tensor cores): Ah,Bh,Dh,Eh = h @ W.T + b ----------------
__global__ __launch_bounds__(256) void k_node_gemm(
    const float* __restrict__ Wa, const float* __restrict__ Wb,
    const float* __restrict__ Wd, const float* __restrict__ We,
    const float* __restrict__ Ba, const float* __restrict__ Bb_,
    const float* __restrict__ Bd, const float* __restrict__ Be)
{
    const float* Wp[4] = {Wa, Wb, Wd, We};
    const float* Bp[4] = {Ba, Bb_, Bd, Be};
    float* Op[4] = {g_Ah, g_Bh, g_Dh, g_Eh};
    extern __shared__ char smc[];
    bf16* ahi = (bf16*)smc;
    bf16* alo = ahi + 128 * SBF;
    bf16* whi = alo + 128 * SBF;
    bf16* wlo = whi + 128 * SBF;

    int tid = threadIdx.x;
    int lane = tid & 31, w = tid >> 5;
    int m0w = (w & 3) * 32, n0w = (w >> 2) * 64;
    int n0 = blockIdx.x * 128;
    int mlim = N_NODES - n0;
    if (mlim > 128) mlim = 128;

    split_tile(g_h + (size_t)n0 * 128, mlim, ahi, alo, tid);

    for (int mat = 0; mat < 4; mat++) {
        __syncthreads();
        split_tile(Wp[mat], 128, whi, wlo, tid);
        __syncthreads();
        float acc[2][8][4];
#pragma unroll
        for (int ms = 0; ms < 2; ms++)
#pragma unroll
            for (int nt = 0; nt < 8; nt++)
#pragma unroll
                for (int j = 0; j < 4; j++) acc[ms][nt][j] = 0.f;

        mma_mainloop(ahi, alo, whi, wlo, m0w, n0w, lane, acc);

        float* Out = Op[mat];
        const float* Bias = Bp[mat];
#pragma unroll
        for (int ms = 0; ms < 2; ms++)
#pragma unroll
            for (int nt = 0; nt < 8; nt++) {
                int col = n0w + nt * 8 + (lane & 3) * 2;
                float2 bv = *(const float2*)(Bias + col);
                int r0 = m0w + ms * 16 + (lane >> 2);
                if (r0 < mlim) {
                    float2 v = {acc[ms][nt][0] + bv.x, acc[ms][nt][1] + bv.y};
                    *(float2*)(Out + (size_t)(n0 + r0) * 128 + col) = v;
                }
                if (r0 + 8 < mlim) {
                    float2 v = {acc[ms][nt][2] + bv.x, acc[ms][nt][3] + bv.y};
                    *(float2*)(Out + (size_t)(n0 + r0 + 8) * 128 + col) = v;
                }
            }
    }
}

// ---------------- edge pass1 (tensor cores): ehat = e@Cw.T + Cb + Dh[dst] + Eh[src]; BN stats --------
__global__ __launch_bounds__(256) void k_edge_pass1(const float* __restrict__ Cw,
                                                    const float* __restrict__ Cb,
                                                    const int* __restrict__ src,
                                                    const int* __restrict__ dst)
{
    extern __shared__ char smc[];
    bf16* ahi = (bf16*)smc;
    bf16* alo = ahi + 128 * SBF;
    bf16* whi = alo + 128 * SBF;
    bf16* wlo = whi + 128 * SBF;
    float* Csm = (float*)smc;                     // alias over ahi/alo after mma
    char* tail = smc + 4 * 128 * SBF * 2;
    int* s_src = (int*)tail;
    int* s_dst = s_src + 128;
    float* ssum = (float*)(s_dst + 128);
    float* ssq = ssum + 128;

    int tid = threadIdx.x;
    int lane = tid & 31, w = tid >> 5;
    int m0w = (w & 3) * 32, n0w = (w >> 2) * 64;
    int e0 = blockIdx.x * 128;

    if (tid < 128) {
        s_src[tid] = src[e0 + tid];
        s_dst[tid] = dst[e0 + tid];
        ssum[tid] = 0.f;
        ssq[tid] = 0.f;
    }
    split_tile(g_e + (size_t)e0 * 128, 128, ahi, alo, tid);
    split_tile(Cw, 128, whi, wlo, tid);
    __syncthreads();

    float acc[2][8][4];
#pragma unroll
    for (int ms = 0; ms < 2; ms++)
#pragma unroll
        for (int nt = 0; nt < 8; nt++)
#pragma unroll
            for (int j = 0; j < 4; j++) acc[ms][nt][j] = 0.f;

    mma_mainloop(ahi, alo, whi, wlo, m0w, n0w, lane, acc);

    __syncthreads();      // A tiles dead; Csm aliases them
#pragma unroll
    for (int ms = 0; ms < 2; ms++)
#pragma unroll
        for (int nt = 0; nt < 8; nt++) {
            int col = n0w + nt * 8 + (lane & 3) * 2;
            int r0 = m0w + ms * 16 + (lane >> 2);
            *(float2*)(Csm + r0 * SCF + col) = make_float2(acc[ms][nt][0], acc[ms][nt][1]);
            *(float2*)(Csm + (r0 + 8) * SCF + col) = make_float2(acc[ms][nt][2], acc[ms][nt][3]);
        }
    __syncthreads();

    int colg = (tid & 31) << 2;
    int r0 = (tid >> 5) << 4;
    float4 cb4 = *(const float4*)(Cb + colg);
    float s0 = 0.f, s1 = 0.f, s2 = 0.f, s3 = 0.f;
    float q0 = 0.f, q1 = 0.f, q2 = 0.f, q3 = 0.f;
#pragma unroll 4
    for (int j = 0; j < 16; j++) {
        int r = r0 + j;
        float4 c = *(const float4*)(Csm + r * SCF + colg);
        int dd = s_dst[r], sr = s_src[r];
        float4 dh = *(const float4*)(g_Dh + (size_t)dd * 128 + colg);
        float4 eh = *(const float4*)(g_Eh + (size_t)sr * 128 + colg);
        float4 v;
        v.x = c.x + cb4.x + dh.x + eh.x;
        v.y = c.y + cb4.y + dh.y + eh.y;
        v.z = c.z + cb4.z + dh.z + eh.z;
        v.w = c.w + cb4.w + dh.w + eh.w;
        *(float4*)(g_ehat + (size_t)(e0 + r) * 128 + colg) = v;
        s0 += v.x; q0 += v.x * v.x;
        s1 += v.y; q1 += v.y * v.y;
        s2 += v.z; q2 += v.z * v.z;
        s3 += v.w; q3 += v.w * v.w;
    }
    atomicAdd(&ssum[colg + 0], s0); atomicAdd(&ssq[colg + 0], q0);
    atomicAdd(&ssum[colg + 1], s1); atomicAdd(&ssq[colg + 1], q1);
    atomicAdd(&ssum[colg + 2], s2); atomicAdd(&ssq[colg + 2], q2);
    atomicAdd(&ssum[colg + 3], s3); atomicAdd(&ssq[colg + 3], q3);
    __syncthreads();
    if (tid < 128) {
        atomicAdd(&g_stats[tid], ssum[tid]);
        atomicAdd(&g_stats[128 + tid], ssq[tid]);
    }
}

// ---------------- fused: e += relu(bn(ehat)); t = Ah + segsum(sig*Bh[src])/(segsum(sig)+eps) --------
__global__ __launch_bounds__(128) void k_agg_fused(const int* __restrict__ src)
{
    int n = blockIdx.x;
    int d = threadIdx.x;
    int beg = g_off[n], end = g_off[n + 1];
    float sc = g_bn_scale[d], sh = g_bn_shift[d];
    float num = 0.f, den = 0.f;
    for (int j = beg; j < end; j++) {
        int eid = g_eids[j];
        float x = g_ehat[(size_t)eid * 128 + d];
        float s = 1.f / (1.f + __expf(-x));
        num += s * g_Bh[(size_t)src[eid] * 128 + d];
        den += s;
        g_e[(size_t)eid * 128 + d] += fmaxf(fmaf(x, sc, sh), 0.f);
    }
    float t = g_Ah[n * 128 + d] + num / (den + EPS_AGG);
    g_t[n * 128 + d] = t;
    atomicAdd(&g_stats[d], t);
    atomicAdd(&g_stats[128 + d], t * t);
}

// ---------------- h += relu(bn(t)) ----------------
__global__ __launch_bounds__(256) void k_node_update()
{
    int i = blockIdx.x * 256 + threadIdx.x;
    int d4 = (i & 31) << 2;
    float4 sc = *(const float4*)(g_bn_scale + d4);
    float4 sh = *(const float4*)(g_bn_shift + d4);
    float4 x = ((const float4*)g_t)[i];
    float4 hv = ((const float4*)g_h)[i];
    hv.x += fmaxf(fmaf(x.x, sc.x, sh.x), 0.f);
    hv.y += fmaxf(fmaf(x.y, sc.y, sh.y), 0.f);
    hv.z += fmaxf(fmaf(x.z, sc.z, sh.z), 0.f);
    hv.w += fmaxf(fmaf(x.w, sc.w, sh.w), 0.f);
    ((float4*)g_h)[i] = hv;
}

// ---------------- decoder ----------------
__global__ __launch_bounds__(256) void k_dec(const float* __restrict__ dw,
                                             const float* __restrict__ db,
                                             const int* __restrict__ src,
                                             const int* __restrict__ dst,
                                             float* __restrict__ out)
{
    int w = (blockIdx.x * 256 + threadIdx.x) >> 5;
    if (w >= N_EDGES) return;
    int lane = threadIdx.x & 31;
    int s = src[w], d = dst[w];
    float4 w1 = *(const float4*)(dw + lane * 4);
    float4 w2 = *(const float4*)(dw + 128 + lane * 4);
    float4 w3 = *(const float4*)(dw + 256 + lane * 4);
    float4 hs = *(const float4*)(g_h + (size_t)s * 128 + lane * 4);
    float4 hd = *(const float4*)(g_h + (size_t)d * 128 + lane * 4);
    float4 ee = *(const float4*)(g_e + (size_t)w * 128 + lane * 4);
    float acc = w1.x * hs.x + w1.y * hs.y + w1.z * hs.z + w1.w * hs.w
              + w2.x * hd.x + w2.y * hd.y + w2.z * hd.z + w2.w * hd.w
              + w3.x * ee.x + w3.y * ee.y + w3.z * ee.z + w3.w * ee.w;
#pragma unroll
    for (int ofs = 16; ofs > 0; ofs >>= 1) acc += __shfl_down_sync(0xffffffffu, acc, ofs);
    if (lane == 0) out[w] = acc + db[0];
}

// ---------------- launcher ----------------
extern "C" void kernel_launch(void* const* d_in, const int* in_sizes, int n_in,
                              void* d_out, int out_size)
{
    const float* emb    = (const float*)d_in[0];
    const float* conv_w = (const float*)d_in[1];
    const float* conv_b = (const float*)d_in[2];
    const float* ee_w   = (const float*)d_in[3];
    const float* ee_b   = (const float*)d_in[4];
    const float* Aw     = (const float*)d_in[5];
    const float* Ab     = (const float*)d_in[6];
    const float* Bw     = (const float*)d_in[7];
    const float* Bb     = (const float*)d_in[8];
    const float* Cw     = (const float*)d_in[9];
    const float* Cb     = (const float*)d_in[10];
    const float* Dw     = (const float*)d_in[11];
    const float* Db     = (const float*)d_in[12];
    const float* Ew     = (const float*)d_in[13];
    const float* Eb     = (const float*)d_in[14];
    const float* bnh_g  = (const float*)d_in[15];
    const float* bnh_b  = (const float*)d_in[16];
    const float* bne_g  = (const float*)d_in[17];
    const float* bne_b  = (const float*)d_in[18];
    const float* dec_w  = (const float*)d_in[19];
    const float* dec_b  = (const float*)d_in[20];
    const float* sim    = (const float*)d_in[21];
    const float* length = (const float*)d_in[22];
    const int*   reads  = (const int*)d_in[23];
    const int*   src    = (const int*)d_in[24];
    const int*   dst    = (const int*)d_in[25];
    float* out = (float*)d_out;

    const int smemG = 4 * 128 * SBF * 2;            // 139264 B (hi/lo A + hi/lo W)
    const int smemE = smemG + 2 * 128 * 4 + 2 * 128 * 4;  // + src/dst + stats = 141312
    const int smemS = (10 * 16 * DIM) * 4 + 2 * 512 * 4;  // 86016
    cudaFuncSetAttribute(k_node_gemm, cudaFuncAttributeMaxDynamicSharedMemorySize, smemG);
    cudaFuncSetAttribute(k_edge_pass1, cudaFuncAttributeMaxDynamicSharedMemorySize, smemE);
    cudaFuncSetAttribute(k_seq, cudaFuncAttributeMaxDynamicSharedMemorySize, smemS);

    const float invE = 1.f / (float)N_EDGES;
    const float invN = 1.f / (float)N_NODES;

    k_wsum<<<40, 256>>>(emb, conv_w);                                   // 0
    k_W2<<<(10 * 16 * DIM + 255) / 256, 256>>>();                       // 1
    k_seq<<<N_NODES / 8, 512, smemS>>>(reads, conv_b);                  // 2
    k_node_gemm<<<(N_NODES + 127) / 128, 256, smemG>>>(                 // 3 <- profiled
        Aw, Bw, Dw, Ew, Ab, Bb, Db, Eb);
    k_edge_enc<<<N_EDGES / 32, 128>>>(sim, length, ee_w, ee_b);         // 4
    k_edge_pass1<<<N_EDGES / 128, 256, smemE>>>(Cw, Cb, src, dst);      // 5

    k_csr_zero<<<(N_NODES + 255) / 256, 256>>>();
    k_hist<<<N_EDGES / 256, 256>>>(dst);
    k_scan<<<1, 1024>>>();
    k_scatter<<<N_EDGES / 256, 256>>>(dst);

    k_bn_final<<<1, 128>>>(bne_g, bne_b, invE);
    k_agg_fused<<<N_NODES, 128>>>(src);
    k_bn_final<<<1, 128>>>(bnh_g, bnh_b, invN);
    k_node_update<<<(N_NODES * 32) / 256, 256>>>();

    for (int i = 1; i < N_LAYERS; i++) {
        const int wo = i * DIM * DIM, bo = i * DIM;
        k_node_gemm<<<(N_NODES + 127) / 128, 256, smemG>>>(
            Aw + wo, Bw + wo, Dw + wo, Ew + wo,
            Ab + bo, Bb + bo, Db + bo, Eb + bo);
        k_edge_pass1<<<N_EDGES / 128, 256, smemE>>>(Cw + wo, Cb + bo, src, dst);
        k_bn_final<<<1, 128>>>(bne_g + bo, bne_b + bo, invE);
        k_agg_fused<<<N_NODES, 128>>>(src);
        k_bn_final<<<1, 128>>>(bnh_g + bo, bnh_b + bo, invN);
        k_node_update<<<(N_NODES * 32) / 256, 256>>>();
    }
    k_dec<<<(N_EDGES * 32 + 255) / 256, 256>>>(dec_w, dec_b, src, dst, out);
}

// round 6
// speedup vs baseline: 1.5303x; 1.4164x over previous
#include <cuda_runtime.h>
#include <cuda_bf16.h>
#include <cstdint>

#define N_NODES 20000
#define READ_LEN 64
#define N_EDGES 320000
#define DIM 128
#define KSZ 20
#define CONV_T (READ_LEN - KSZ + 1)
#define N_LAYERS 4
#define EPS_BN 1e-5f
#define EPS_AGG 1e-6f

typedef __nv_bfloat16 bf16;
typedef unsigned long long ull;

#define SBF 136   // bf16 smem row stride: 272B -> ldmatrix conflict-free
#define SCF 132   // fp32 C smem row stride

// ---------------- device scratch ----------------
__device__ float g_h[N_NODES * DIM];
__device__ float g_e[(size_t)N_EDGES * DIM];
__device__ float g_ehat[(size_t)N_EDGES * DIM];
__device__ float g_Ah[N_NODES * DIM];
__device__ float g_Bh[N_NODES * DIM];
__device__ float g_Dh[N_NODES * DIM];
__device__ float g_Eh[N_NODES * DIM];
__device__ float g_t[N_NODES * DIM];
__device__ float g_wsum[4 * KSZ * DIM];
__device__ float g_W2[10 * 16 * DIM];
__device__ float g_stats[2 * DIM];        // zero-init; bn_final restores zeros
__device__ float g_bn_scale[DIM];
__device__ float g_bn_shift[DIM];
__device__ int g_cnt[N_NODES];
__device__ int g_off[N_NODES + 1];
__device__ int g_cur[N_NODES];
__device__ int g_eids[N_EDGES];

// ---------------- mma helpers ----------------
__device__ __forceinline__ unsigned s2u(const void* p)
{
    return (unsigned)__cvta_generic_to_shared(p);
}
__device__ __forceinline__ void ldsm4(unsigned* r, unsigned addr)
{
    asm volatile("ldmatrix.sync.aligned.m8n8.x4.shared.b16 {%0,%1,%2,%3}, [%4];"
                 : "=r"(r[0]), "=r"(r[1]), "=r"(r[2]), "=r"(r[3]) : "r"(addr));
}
__device__ __forceinline__ void mma16816(float* c, const unsigned* a, const unsigned* b)
{
    asm volatile("mma.sync.aligned.m16n8k16.row.col.f32.bf16.bf16.f32 "
                 "{%0,%1,%2,%3}, {%4,%5,%6,%7}, {%8,%9}, {%0,%1,%2,%3};"
                 : "+f"(c[0]), "+f"(c[1]), "+f"(c[2]), "+f"(c[3])
                 : "r"(a[0]), "r"(a[1]), "r"(a[2]), "r"(a[3]), "r"(b[0]), "r"(b[1]));
}
__device__ __forceinline__ unsigned pb2(float a, float b)
{
    __nv_bfloat162 t = __floats2bfloat162_rn(a, b);
    return *(unsigned*)&t;
}

// split fp32 tile [rows<=128][128] (row stride 128) into hi/lo bf16 smem tiles (512 threads)
__device__ __forceinline__ void split_tile(const float* __restrict__ g, int rows,
                                           bf16* hi, bf16* lo, int tid)
{
#pragma unroll
    for (int i = tid; i < 128 * 32; i += 512) {
        int r = i >> 5, c = (i & 31) << 2;
        float4 v = make_float4(0.f, 0.f, 0.f, 0.f);
        if (r < rows) v = *(const float4*)(g + r * 128 + c);
        float hx = __bfloat162float(__float2bfloat16(v.x));
        float hy = __bfloat162float(__float2bfloat16(v.y));
        float hz = __bfloat162float(__float2bfloat16(v.z));
        float hw = __bfloat162float(__float2bfloat16(v.w));
        uint2 hp = make_uint2(pb2(hx, hy), pb2(hz, hw));
        uint2 lp = make_uint2(pb2(v.x - hx, v.y - hy), pb2(v.z - hz, v.w - hw));
        *(uint2*)(hi + r * SBF + c) = hp;
        *(uint2*)(lo + r * SBF + c) = lp;
    }
}

// mainloop (per warp, 32x32 tile): acc += Ahi*Bhi + Ahi*Blo + Alo*Bhi
__device__ __forceinline__ void mma_mainloop(const bf16* ahi, const bf16* alo,
                                             const bf16* whi, const bf16* wlo,
                                             int m0w, int n0w, int lane,
                                             float acc[2][4][4])
{
    int aoff = (lane & 15) * SBF + (lane >> 4) * 8;
    int boff = ((lane & 7) + ((lane >> 4) << 3)) * SBF + ((lane >> 3) & 1) * 8;
#pragma unroll
    for (int kt = 0; kt < 8; kt++) {
        unsigned af[2][2][4], bf[2][2][4];
#pragma unroll
        for (int ms = 0; ms < 2; ms++) {
            int o = (m0w + ms * 16) * SBF + aoff + kt * 16;
            ldsm4(af[0][ms], s2u(ahi + o));
            ldsm4(af[1][ms], s2u(alo + o));
        }
#pragma unroll
        for (int np = 0; np < 2; np++) {
            int o = (n0w + np * 16) * SBF + boff + kt * 16;
            ldsm4(bf[0][np], s2u(whi + o));
            ldsm4(bf[1][np], s2u(wlo + o));
        }
#pragma unroll
        for (int ms = 0; ms < 2; ms++)
#pragma unroll
            for (int nt = 0; nt < 4; nt++)
                mma16816(acc[ms][nt], af[0][ms], &bf[0][nt >> 1][(nt & 1) * 2]);
#pragma unroll
        for (int ms = 0; ms < 2; ms++)
#pragma unroll
            for (int nt = 0; nt < 4; nt++)
                mma16816(acc[ms][nt], af[0][ms], &bf[1][nt >> 1][(nt & 1) * 2]);
#pragma unroll
        for (int ms = 0; ms < 2; ms++)
#pragma unroll
            for (int nt = 0; nt < 4; nt++)
                mma16816(acc[ms][nt], af[1][ms], &bf[0][nt >> 1][(nt & 1) * 2]);
    }
}

// ---------------- sequence encoder ----------------
__global__ void k_wsum(const float* __restrict__ emb, const float* __restrict__ cw)
{
    int idx = blockIdx.x * 256 + threadIdx.x;
    if (idx >= 4 * KSZ * DIM) return;
    int d = idx & 127;
    int bk = idx >> 7;
    int k = bk % KSZ, b = bk / KSZ;
    float s = 0.f;
#pragma unroll
    for (int c = 0; c < 3; c++) s += emb[b * 3 + c] * cw[d * 3 * KSZ + c * KSZ + k];
    g_wsum[idx] = s;
}

__global__ void k_W2()
{
    int idx = blockIdx.x * 256 + threadIdx.x;
    if (idx >= 10 * 16 * DIM) return;
    int d = idx & 127;
    int r = idx >> 7;
    int c2 = r & 15, k2 = r >> 4;
    int a = c2 >> 2, b = c2 & 3;
    g_W2[idx] = g_wsum[(a * KSZ + 2 * k2) * DIM + d] + g_wsum[(b * KSZ + 2 * k2 + 1) * DIM + d];
}

__global__ __launch_bounds__(512) void k_seq(const int* __restrict__ reads,
                                             const float* __restrict__ conv_b)
{
    extern __shared__ float sm[];
    float* sW2 = sm;
    int* scode = (int*)(sm + 10 * 16 * DIM);
    int* spc = scode + 512;
    int tid = threadIdx.x;

    for (int i = tid; i < (10 * 16 * DIM) / 4; i += 512)
        ((float4*)sW2)[i] = ((const float4*)g_W2)[i];

    int nl = tid >> 6, l = tid & 63;
    int n = blockIdx.x * 8 + nl;
    scode[tid] = reads[n * READ_LEN + l];
    __syncthreads();
    if (l < 63) spc[tid] = (scode[tid] * 4 + scode[tid + 1]) << 7;
    __syncthreads();

    int dp = tid & 63;
    const float* wd = sW2 + dp * 2;
    const int* pc = spc + nl * 64;
    float m0 = -3.4e38f, m1 = -3.4e38f;
#pragma unroll
    for (int t = 0; t < CONV_T; t++) {
        float s0 = 0.f, s1 = 0.f;
#pragma unroll
        for (int k2 = 0; k2 < 10; k2++) {
            float2 v = *(const float2*)(wd + pc[t + 2 * k2] + k2 * 2048);
            s0 += v.x; s1 += v.y;
        }
        m0 = fmaxf(m0, s0);
        m1 = fmaxf(m1, s1);
    }
    float2 bv = *(const float2*)(conv_b + dp * 2);
    float2 hv;
    hv.x = fmaxf(m0 + bv.x, 0.f);
    hv.y = fmaxf(m1 + bv.y, 0.f);
    *(float2*)(g_h + n * DIM + dp * 2) = hv;
}

// ---------------- edge encoder ----------------
__global__ __launch_bounds__(128) void k_edge_enc(const float* __restrict__ sim,
                                                  const float* __restrict__ len,
                                                  const float* __restrict__ ew,
                                                  const float* __restrict__ eb)
{
    int d = threadIdx.x;
    float w0 = ew[d * 2], w1 = ew[d * 2 + 1], b = eb[d];
    int e0 = blockIdx.x * 32;
#pragma unroll 4
    for (int j = 0; j < 32; j++) {
        int eid = e0 + j;
        g_e[(size_t)eid * DIM + d] = fmaf(sim[eid], w0, fmaf(len[eid], w1, b));
    }
}

// ---------------- CSR build by dst ----------------
__global__ void k_csr_zero()
{
    int i = blockIdx.x * 256 + threadIdx.x;
    if (i < N_NODES) g_cnt[i] = 0;
}
__global__ void k_hist(const int* __restrict__ dst)
{
    int i = blockIdx.x * 256 + threadIdx.x;
    if (i < N_EDGES) atomicAdd(&g_cnt[dst[i]], 1);
}
__global__ __launch_bounds__(1024) void k_scan()
{
    __shared__ int sd[1024];
    int tid = threadIdx.x;
    int carry = 0;
    for (int base = 0; base < N_NODES; base += 1024) {
        int i = base + tid;
        int v = (i < N_NODES) ? g_cnt[i] : 0;
        __syncthreads();
        sd[tid] = v;
        __syncthreads();
        for (int ofs = 1; ofs < 1024; ofs <<= 1) {
            int t = (tid >= ofs) ? sd[tid - ofs] : 0;
            __syncthreads();
            sd[tid] += t;
            __syncthreads();
        }
        if (i < N_NODES) {
            int ex = carry + sd[tid] - v;
            g_off[i] = ex;
            g_cur[i] = ex;
        }
        carry += sd[1023];
    }
    if (tid == 0) g_off[N_NODES] = carry;
}
__global__ void k_scatter(const int* __restrict__ dst)
{
    int i = blockIdx.x * 256 + threadIdx.x;
    if (i < N_EDGES) {
        int p = atomicAdd(&g_cur[dst[i]], 1);
        g_eids[p] = i;
    }
}

// ---------------- BN finalize (restores g_stats zero invariant) ----------------
__global__ __launch_bounds__(128) void k_bn_final(const float* __restrict__ g,
                                                  const float* __restrict__ b,
                                                  float invc)
{
    int d = threadIdx.x;
    float s = g_stats[d], sq = g_stats[128 + d];
    float mean = s * invc;
    float var = sq * invc - mean * mean;
    float sc = g[d] * rsqrtf(var + EPS_BN);
    g_bn_scale[d] = sc;
    g_bn_shift[d] = b[d] - mean * sc;
    g_stats[d] = 0.f;
    g_stats[128 + d] = 0.f;
}

// ---------------- node GEMM (tensor cores, 512 thr): Ah,Bh,Dh,Eh = h @ W.T + b ----------------
__global__ __launch_bounds__(512) void k_node_gemm(
    const float* __restrict__ Wa, const float* __restrict__ Wb,
    const float* __restrict__ Wd, const float* __restrict__ We,
    const float* __restrict__ Ba, const float* __restrict__ Bb_,
    const float* __restrict__ Bd, const float* __restrict__ Be)
{
    const float* Wp[4] = {Wa, Wb, Wd, We};
    const float* Bp[4] = {Ba, Bb_, Bd, Be};
    float* Op[4] = {g_Ah, g_Bh, g_Dh, g_Eh};
    extern __shared__ char smc[];
    bf16* ahi = (bf16*)smc;
    bf16* alo = ahi + 128 * SBF;
    bf16* whi = alo + 128 * SBF;
    bf16* wlo = whi + 128 * SBF;

    int tid = threadIdx.x;
    int lane = tid & 31, w = tid >> 5;
    int m0w = (w & 3) * 32, n0w = (w >> 2) * 32;
    int n0 = blockIdx.x * 128;
    int mlim = N_NODES - n0;
    if (mlim > 128) mlim = 128;

    split_tile(g_h + (size_t)n0 * 128, mlim, ahi, alo, tid);

    for (int mat = 0; mat < 4; mat++) {
        __syncthreads();
        split_tile(Wp[mat], 128, whi, wlo, tid);
        __syncthreads();
        float acc[2][4][4];
#pragma unroll
        for (int ms = 0; ms < 2; ms++)
#pragma unroll
            for (int nt = 0; nt < 4; nt++)
#pragma unroll
                for (int j = 0; j < 4; j++) acc[ms][nt][j] = 0.f;

        mma_mainloop(ahi, alo, whi, wlo, m0w, n0w, lane, acc);

        float* Out = Op[mat];
        const float* Bias = Bp[mat];
#pragma unroll
        for (int ms = 0; ms < 2; ms++)
#pragma unroll
            for (int nt = 0; nt < 4; nt++) {
                int col = n0w + nt * 8 + (lane & 3) * 2;
                float2 bv = *(const float2*)(Bias + col);
                int r0 = m0w + ms * 16 + (lane >> 2);
                if (r0 < mlim) {
                    float2 v = {acc[ms][nt][0] + bv.x, acc[ms][nt][1] + bv.y};
                    *(float2*)(Out + (size_t)(n0 + r0) * 128 + col) = v;
                }
                if (r0 + 8 < mlim) {
                    float2 v = {acc[ms][nt][2] + bv.x, acc[ms][nt][3] + bv.y};
                    *(float2*)(Out + (size_t)(n0 + r0 + 8) * 128 + col) = v;
                }
            }
    }
}

// ---------------- edge pass1 (tensor cores, 512 thr) ----------------
__global__ __launch_bounds__(512) void k_edge_pass1(const float* __restrict__ Cw,
                                                    const float* __restrict__ Cb,
                                                    const int* __restrict__ src,
                                                    const int* __restrict__ dst)
{
    extern __shared__ char smc[];
    bf16* ahi = (bf16*)smc;
    bf16* alo = ahi + 128 * SBF;
    bf16* whi = alo + 128 * SBF;
    bf16* wlo = whi + 128 * SBF;
    float* Csm = (float*)smc;                     // aliases A tiles after mma
    char* tail = smc + 4 * 128 * SBF * 2;
    int* s_src = (int*)tail;
    int* s_dst = s_src + 128;
    float* ssum = (float*)(s_dst + 128);
    float* ssq = ssum + 128;

    int tid = threadIdx.x;
    int lane = tid & 31, w = tid >> 5;
    int m0w = (w & 3) * 32, n0w = (w >> 2) * 32;
    int e0 = blockIdx.x * 128;

    if (tid < 128) {
        s_src[tid] = src[e0 + tid];
        s_dst[tid] = dst[e0 + tid];
        ssum[tid] = 0.f;
        ssq[tid] = 0.f;
    }
    split_tile(g_e + (size_t)e0 * 128, 128, ahi, alo, tid);
    split_tile(Cw, 128, whi, wlo, tid);
    __syncthreads();

    float acc[2][4][4];
#pragma unroll
    for (int ms = 0; ms < 2; ms++)
#pragma unroll
        for (int nt = 0; nt < 4; nt++)
#pragma unroll
            for (int j = 0; j < 4; j++) acc[ms][nt][j] = 0.f;

    mma_mainloop(ahi, alo, whi, wlo, m0w, n0w, lane, acc);

    __syncthreads();      // A tiles dead; Csm aliases them
#pragma unroll
    for (int ms = 0; ms < 2; ms++)
#pragma unroll
        for (int nt = 0; nt < 4; nt++) {
            int col = n0w + nt * 8 + (lane & 3) * 2;
            int r0 = m0w + ms * 16 + (lane >> 2);
            *(float2*)(Csm + r0 * SCF + col) = make_float2(acc[ms][nt][0], acc[ms][nt][1]);
            *(float2*)(Csm + (r0 + 8) * SCF + col) = make_float2(acc[ms][nt][2], acc[ms][nt][3]);
        }
    __syncthreads();

    int colg = (tid & 31) << 2;
    int r0 = (tid >> 5) << 3;       // 16 warps x 8 rows
    float4 cb4 = *(const float4*)(Cb + colg);
    float s0 = 0.f, s1 = 0.f, s2 = 0.f, s3 = 0.f;
    float q0 = 0.f, q1 = 0.f, q2 = 0.f, q3 = 0.f;
#pragma unroll
    for (int j = 0; j < 8; j++) {
        int r = r0 + j;
        float4 c = *(const float4*)(Csm + r * SCF + colg);
        int dd = s_dst[r], sr = s_src[r];
        float4 dh = *(const float4*)(g_Dh + (size_t)dd * 128 + colg);
        float4 eh = *(const float4*)(g_Eh + (size_t)sr * 128 + colg);
        float4 v;
        v.x = c.x + cb4.x + dh.x + eh.x;
        v.y = c.y + cb4.y + dh.y + eh.y;
        v.z = c.z + cb4.z + dh.z + eh.z;
        v.w = c.w + cb4.w + dh.w + eh.w;
        *(float4*)(g_ehat + (size_t)(e0 + r) * 128 + colg) = v;
        s0 += v.x; q0 += v.x * v.x;
        s1 += v.y; q1 += v.y * v.y;
        s2 += v.z; q2 += v.z * v.z;
        s3 += v.w; q3 += v.w * v.w;
    }
    atomicAdd(&ssum[colg + 0], s0); atomicAdd(&ssq[colg + 0], q0);
    atomicAdd(&ssum[colg + 1], s1); atomicAdd(&ssq[colg + 1], q1);
    atomicAdd(&ssum[colg + 2], s2); atomicAdd(&ssq[colg + 2], q2);
    atomicAdd(&ssum[colg + 3], s3); atomicAdd(&ssq[colg + 3], q3);
    __syncthreads();
    if (tid < 128) {
        atomicAdd(&g_stats[tid], ssum[tid]);
        atomicAdd(&g_stats[128 + tid], ssq[tid]);
    }
}

// ---------------- fused: e += relu(bn(ehat)); t = Ah + segsum(sig*Bh[src])/(segsum(sig)+eps) --------
__global__ __launch_bounds__(128) void k_agg_fused(const int* __restrict__ src)
{
    int n = blockIdx.x;
    int d = threadIdx.x;
    int beg = g_off[n], end = g_off[n + 1];
    float sc = g_bn_scale[d], sh = g_bn_shift[d];
    float num = 0.f, den = 0.f;
    for (int j = beg; j < end; j++) {
        int eid = g_eids[j];
        float x = g_ehat[(size_t)eid * 128 + d];
        float s = 1.f / (1.f + __expf(-x));
        num += s * g_Bh[(size_t)src[eid] * 128 + d];
        den += s;
        g_e[(size_t)eid * 128 + d] += fmaxf(fmaf(x, sc, sh), 0.f);
    }
    float t = g_Ah[n * 128 + d] + num / (den + EPS_AGG);
    g_t[n * 128 + d] = t;
    atomicAdd(&g_stats[d], t);
    atomicAdd(&g_stats[128 + d], t * t);
}

// ---------------- h += relu(bn(t)) ----------------
__global__ __launch_bounds__(256) void k_node_update()
{
    int i = blockIdx.x * 256 + threadIdx.x;
    int d4 = (i & 31) << 2;
    float4 sc = *(const float4*)(g_bn_scale + d4);
    float4 sh = *(const float4*)(g_bn_shift + d4);
    float4 x = ((const float4*)g_t)[i];
    float4 hv = ((const float4*)g_h)[i];
    hv.x += fmaxf(fmaf(x.x, sc.x, sh.x), 0.f);
    hv.y += fmaxf(fmaf(x.y, sc.y, sh.y), 0.f);
    hv.z += fmaxf(fmaf(x.z, sc.z, sh.z), 0.f);
    hv.w += fmaxf(fmaf(x.w, sc.w, sh.w), 0.f);
    ((float4*)g_h)[i] = hv;
}

// ---------------- decoder ----------------
__global__ __launch_bounds__(256) void k_dec(const float* __restrict__ dw,
                                             const float* __restrict__ db,
                                             const int* __restrict__ src,
                                             const int* __restrict__ dst,
                                             float* __restrict__ out)
{
    int w = (blockIdx.x * 256 + threadIdx.x) >> 5;
    if (w >= N_EDGES) return;
    int lane = threadIdx.x & 31;
    int s = src[w], d = dst[w];
    float4 w1 = *(const float4*)(dw + lane * 4);
    float4 w2 = *(const float4*)(dw + 128 + lane * 4);
    float4 w3 = *(const float4*)(dw + 256 + lane * 4);
    float4 hs = *(const float4*)(g_h + (size_t)s * 128 + lane * 4);
    float4 hd = *(const float4*)(g_h + (size_t)d * 128 + lane * 4);
    float4 ee = *(const float4*)(g_e + (size_t)w * 128 + lane * 4);
    float acc = w1.x * hs.x + w1.y * hs.y + w1.z * hs.z + w1.w * hs.w
              + w2.x * hd.x + w2.y * hd.y + w2.z * hd.z + w2.w * hd.w
              + w3.x * ee.x + w3.y * ee.y + w3.z * ee.z + w3.w * ee.w;
#pragma unroll
    for (int ofs = 16; ofs > 0; ofs >>= 1) acc += __shfl_down_sync(0xffffffffu, acc, ofs);
    if (lane == 0) out[w] = acc + db[0];
}

// ---------------- launcher ----------------
extern "C" void kernel_launch(void* const* d_in, const int* in_sizes, int n_in,
                              void* d_out, int out_size)
{
    const float* emb    = (const float*)d_in[0];
    const float* conv_w = (const float*)d_in[1];
    const float* conv_b = (const float*)d_in[2];
    const float* ee_w   = (const float*)d_in[3];
    const float* ee_b   = (const float*)d_in[4];
    const float* Aw     = (const float*)d_in[5];
    const float* Ab     = (const float*)d_in[6];
    const float* Bw     = (const float*)d_in[7];
    const float* Bb     = (const float*)d_in[8];
    const float* Cw     = (const float*)d_in[9];
    const float* Cb     = (const float*)d_in[10];
    const float* Dw     = (const float*)d_in[11];
    const float* Db     = (const float*)d_in[12];
    const float* Ew     = (const float*)d_in[13];
    const float* Eb     = (const float*)d_in[14];
    const float* bnh_g  = (const float*)d_in[15];
    const float* bnh_b  = (const float*)d_in[16];
    const float* bne_g  = (const float*)d_in[17];
    const float* bne_b  = (const float*)d_in[18];
    const float* dec_w  = (const float*)d_in[19];
    const float* dec_b  = (const float*)d_in[20];
    const float* sim    = (const float*)d_in[21];
    const float* length = (const float*)d_in[22];
    const int*   reads  = (const int*)d_in[23];
    const int*   src    = (const int*)d_in[24];
    const int*   dst    = (const int*)d_in[25];
    float* out = (float*)d_out;

    const int smemG = 4 * 128 * SBF * 2;                  // 139264
    const int smemE = smemG + 2 * 128 * 4 + 2 * 128 * 4;  // 141312
    const int smemS = (10 * 16 * DIM) * 4 + 2 * 512 * 4;  // 86016
    cudaFuncSetAttribute(k_node_gemm, cudaFuncAttributeMaxDynamicSharedMemorySize, smemG);
    cudaFuncSetAttribute(k_edge_pass1, cudaFuncAttributeMaxDynamicSharedMemorySize, smemE);
    cudaFuncSetAttribute(k_seq, cudaFuncAttributeMaxDynamicSharedMemorySize, smemS);

    const float invE = 1.f / (float)N_EDGES;
    const float invN = 1.f / (float)N_NODES;

    k_wsum<<<40, 256>>>(emb, conv_w);                                   // 0
    k_W2<<<(10 * 16 * DIM + 255) / 256, 256>>>();                       // 1
    k_seq<<<N_NODES / 8, 512, smemS>>>(reads, conv_b);                  // 2
    k_node_gemm<<<(N_NODES + 127) / 128, 512, smemG>>>(                 // 3 <- profiled
        Aw, Bw, Dw, Ew, Ab, Bb, Db, Eb);
    k_edge_enc<<<N_EDGES / 32, 128>>>(sim, length, ee_w, ee_b);         // 4
    k_edge_pass1<<<N_EDGES / 128, 512, smemE>>>(Cw, Cb, src, dst);      // 5

    k_csr_zero<<<(N_NODES + 255) / 256, 256>>>();
    k_hist<<<N_EDGES / 256, 256>>>(dst);
    k_scan<<<1, 1024>>>();
    k_scatter<<<N_EDGES / 256, 256>>>(dst);

    k_bn_final<<<1, 128>>>(bne_g, bne_b, invE);
    k_agg_fused<<<N_NODES, 128>>>(src);
    k_bn_final<<<1, 128>>>(bnh_g, bnh_b, invN);
    k_node_update<<<(N_NODES * 32) / 256, 256>>>();

    for (int i = 1; i < N_LAYERS; i++) {
        const int wo = i * DIM * DIM, bo = i * DIM;
        k_node_gemm<<<(N_NODES + 127) / 128, 512, smemG>>>(
            Aw + wo, Bw + wo, Dw + wo, Ew + wo,
            Ab + bo, Bb + bo, Db + bo, Eb + bo);
        k_edge_pass1<<<N_EDGES / 128, 512, smemE>>>(Cw + wo, Cb + bo, src, dst);
        k_bn_final<<<1, 128>>>(bne_g + bo, bne_b + bo, invE);
        k_agg_fused<<<N_NODES, 128>>>(src);
        k_bn_final<<<1, 128>>>(bnh_g + bo, bnh_b + bo, invN);
        k_node_update<<<(N_NODES * 32) / 256, 256>>>();
    }
    k_dec<<<(N_EDGES * 32 + 255) / 256, 256>>>(dec_w, dec_b, src, dst, out);
}

// round 9
// speedup vs baseline: 1.7134x; 1.1197x over previous
#include <cuda_runtime.h>
#include <cuda_fp16.h>
#include <cstdint>

#define N_NODES 20000
#define READ_LEN 64
#define N_EDGES 320000
#define DIM 128
#define KSZ 20
#define CONV_T (READ_LEN - KSZ + 1)
#define N_LAYERS 4
#define EPS_BN 1e-5f
#define EPS_AGG 1e-6f

#define SBF 136   // half smem row stride (272B): 16B-aligned rows, ldsm conflict-free
#define SCF 132   // fp32 C smem row stride

// ---------------- device scratch ----------------
__device__ float g_h[N_NODES * DIM];
__device__ float g_e[(size_t)N_EDGES * DIM];
__device__ half  g_ehat[(size_t)N_EDGES * DIM];      // fp16 ehat
__device__ float g_Ah[N_NODES * DIM];
__device__ float g_Bh[N_NODES * DIM];
__device__ float g_Dh[N_NODES * DIM];
__device__ float g_Eh[N_NODES * DIM];
__device__ float g_t[N_NODES * DIM];
__device__ float g_wsum[4 * KSZ * DIM];
__device__ float g_W2[10 * 16 * DIM];
__device__ half  g_Whi[20 * 128 * SBF];              // pre-split weights (smem image)
__device__ float g_stats[2 * DIM];                   // zero-init; bn_final restores zeros
__device__ float g_bn_scale[DIM];
__device__ float g_bn_shift[DIM];
__device__ int g_cnt[N_NODES];
__device__ int g_off[N_NODES + 1];
__device__ int g_cur[N_NODES];
__device__ int g_eids[N_EDGES];

// ---------------- mma helpers ----------------
__device__ __forceinline__ unsigned s2u(const void* p)
{
    return (unsigned)__cvta_generic_to_shared(p);
}
__device__ __forceinline__ void ldsm4(unsigned* r, unsigned addr)
{
    asm volatile("ldmatrix.sync.aligned.m8n8.x4.shared.b16 {%0,%1,%2,%3}, [%4];"
                 : "=r"(r[0]), "=r"(r[1]), "=r"(r[2]), "=r"(r[3]) : "r"(addr));
}
__device__ __forceinline__ void mma16816(float* c, const unsigned* a, const unsigned* b)
{
    asm volatile("mma.sync.aligned.m16n8k16.row.col.f32.f16.f16.f32 "
                 "{%0,%1,%2,%3}, {%4,%5,%6,%7}, {%8,%9}, {%0,%1,%2,%3};"
                 : "+f"(c[0]), "+f"(c[1]), "+f"(c[2]), "+f"(c[3])
                 : "r"(a[0]), "r"(a[1]), "r"(a[2]), "r"(a[3]), "r"(b[0]), "r"(b[1]));
}

// split fp32 tile [rows<=128][128] into hi/lo fp16 smem tiles (512 threads)
__device__ __forceinline__ void split_tileA(const float* __restrict__ g, int rows,
                                            half* hi, half* lo, int tid)
{
#pragma unroll
    for (int i = tid; i < 128 * 32; i += 512) {
        int r = i >> 5, c = (i & 31) << 2;
        float4 v = make_float4(0.f, 0.f, 0.f, 0.f);
        if (r < rows) v = *(const float4*)(g + r * 128 + c);
        half hx = __float2half_rn(v.x), hy = __float2half_rn(v.y);
        half hz = __float2half_rn(v.z), hw = __float2half_rn(v.w);
        half2 hp0 = __halves2half2(hx, hy), hp1 = __halves2half2(hz, hw);
        half2 lp0 = __floats2half2_rn(v.x - __half2float(hx), v.y - __half2float(hy));
        half2 lp1 = __floats2half2_rn(v.z - __half2float(hz), v.w - __half2float(hw));
        *(uint2*)(hi + r * SBF + c) = make_uint2(*(unsigned*)&hp0, *(unsigned*)&hp1);
        *(uint2*)(lo + r * SBF + c) = make_uint2(*(unsigned*)&lp0, *(unsigned*)&lp1);
    }
}

// mainloop (per warp, 32x32 tile): acc += Ahi*Whi + Alo*Whi
__device__ __forceinline__ void mma_mainloop(const half* ahi, const half* alo,
                                             const half* whi,
                                             int m0w, int n0w, int lane,
                                             float acc[2][4][4])
{
    int aoff = (lane & 15) * SBF + (lane >> 4) * 8;
    int boff = ((lane & 7) + ((lane >> 4) << 3)) * SBF + ((lane >> 3) & 1) * 8;
#pragma unroll
    for (int kt = 0; kt < 8; kt++) {
        unsigned af[2][2][4], bf[2][4];
#pragma unroll
        for (int ms = 0; ms < 2; ms++) {
            int o = (m0w + ms * 16) * SBF + aoff + kt * 16;
            ldsm4(af[0][ms], s2u(ahi + o));
            ldsm4(af[1][ms], s2u(alo + o));
        }
#pragma unroll
        for (int np = 0; np < 2; np++) {
            int o = (n0w + np * 16) * SBF + boff + kt * 16;
            ldsm4(bf[np], s2u(whi + o));
        }
#pragma unroll
        for (int ms = 0; ms < 2; ms++)
#pragma unroll
            for (int nt = 0; nt < 4; nt++)
                mma16816(acc[ms][nt], af[0][ms], &bf[nt >> 1][(nt & 1) * 2]);
#pragma unroll
        for (int ms = 0; ms < 2; ms++)
#pragma unroll
            for (int nt = 0; nt < 4; nt++)
                mma16816(acc[ms][nt], af[1][ms], &bf[nt >> 1][(nt & 1) * 2]);
    }
}

// ---------------- prep: conv wsum + weight pre-split ----------------
// blocks 0..39: wsum; blocks 40..59: split one of 20 weight mats to fp16 smem-image
__global__ void k_prep(const float* __restrict__ emb, const float* __restrict__ cw,
                       const float* __restrict__ Aw, const float* __restrict__ Bw,
                       const float* __restrict__ Cw, const float* __restrict__ Dw,
                       const float* __restrict__ Ew)
{
    int bx = blockIdx.x, tid = threadIdx.x;
    if (bx < 40) {
        int idx = bx * 256 + tid;
        if (idx >= 4 * KSZ * DIM) return;
        int d = idx & 127;
        int bk = idx >> 7;
        int k = bk % KSZ, b = bk / KSZ;
        float s = 0.f;
#pragma unroll
        for (int c = 0; c < 3; c++) s += emb[b * 3 + c] * cw[d * 3 * KSZ + c * KSZ + k];
        g_wsum[idx] = s;
    } else {
        int m = bx - 40;             // 0..19
        int lay = m / 5, which = m % 5;
        const float* srcs[5] = {Aw, Bw, Dw, Ew, Cw};
        const float* src = srcs[which] + lay * DIM * DIM;
        half* dst = g_Whi + (size_t)m * 128 * SBF;
        for (int i = tid; i < 128 * 128; i += 256) {
            int r = i >> 7, c = i & 127;
            dst[r * SBF + c] = __float2half_rn(src[i]);
        }
    }
}

__global__ void k_W2()
{
    int idx = blockIdx.x * 256 + threadIdx.x;
    if (idx >= 10 * 16 * DIM) return;
    int d = idx & 127;
    int r = idx >> 7;
    int c2 = r & 15, k2 = r >> 4;
    int a = c2 >> 2, b = c2 & 3;
    g_W2[idx] = g_wsum[(a * KSZ + 2 * k2) * DIM + d] + g_wsum[(b * KSZ + 2 * k2 + 1) * DIM + d];
}

__global__ __launch_bounds__(512) void k_seq(const int* __restrict__ reads,
                                             const float* __restrict__ conv_b)
{
    extern __shared__ float sm[];
    float* sW2 = sm;
    int* scode = (int*)(sm + 10 * 16 * DIM);
    int* spc = scode + 512;
    int tid = threadIdx.x;

    for (int i = tid; i < (10 * 16 * DIM) / 4; i += 512)
        ((float4*)sW2)[i] = ((const float4*)g_W2)[i];

    int nl = tid >> 6, l = tid & 63;
    int n = blockIdx.x * 8 + nl;
    scode[tid] = reads[n * READ_LEN + l];
    __syncthreads();
    if (l < 63) spc[tid] = (scode[tid] * 4 + scode[tid + 1]) << 7;
    __syncthreads();

    int dp = tid & 63;
    const float* wd = sW2 + dp * 2;
    const int* pc = spc + nl * 64;
    float m0 = -3.4e38f, m1 = -3.4e38f;
#pragma unroll
    for (int t = 0; t < CONV_T; t++) {
        float s0 = 0.f, s1 = 0.f;
#pragma unroll
        for (int k2 = 0; k2 < 10; k2++) {
            float2 v = *(const float2*)(wd + pc[t + 2 * k2] + k2 * 2048);
            s0 += v.x; s1 += v.y;
        }
        m0 = fmaxf(m0, s0);
        m1 = fmaxf(m1, s1);
    }
    float2 bv = *(const float2*)(conv_b + dp * 2);
    float2 hv;
    hv.x = fmaxf(m0 + bv.x, 0.f);
    hv.y = fmaxf(m1 + bv.y, 0.f);
    *(float2*)(g_h + n * DIM + dp * 2) = hv;
}

// ---------------- edge encoder ----------------
__global__ __launch_bounds__(128) void k_edge_enc(const float* __restrict__ sim,
                                                  const float* __restrict__ len,
                                                  const float* __restrict__ ew,
                                                  const float* __restrict__ eb)
{
    int d = threadIdx.x;
    float w0 = ew[d * 2], w1 = ew[d * 2 + 1], b = eb[d];
    int e0 = blockIdx.x * 32;
#pragma unroll 4
    for (int j = 0; j < 32; j++) {
        int eid = e0 + j;
        g_e[(size_t)eid * DIM + d] = fmaf(sim[eid], w0, fmaf(len[eid], w1, b));
    }
}

// ---------------- CSR build by dst ----------------
__global__ void k_csr_zero()
{
    int i = blockIdx.x * 256 + threadIdx.x;
    if (i < N_NODES) g_cnt[i] = 0;
}
__global__ void k_hist(const int* __restrict__ dst)
{
    int i = blockIdx.x * 256 + threadIdx.x;
    if (i < N_EDGES) atomicAdd(&g_cnt[dst[i]], 1);
}
__global__ __launch_bounds__(1024) void k_scan()
{
    __shared__ int sd[1024];
    int tid = threadIdx.x;
    int carry = 0;
    for (int base = 0; base < N_NODES; base += 1024) {
        int i = base + tid;
        int v = (i < N_NODES) ? g_cnt[i] : 0;
        __syncthreads();
        sd[tid] = v;
        __syncthreads();
        for (int ofs = 1; ofs < 1024; ofs <<= 1) {
            int t = (tid >= ofs) ? sd[tid - ofs] : 0;
            __syncthreads();
            sd[tid] += t;
            __syncthreads();
        }
        if (i < N_NODES) {
            int ex = carry + sd[tid] - v;
            g_off[i] = ex;
            g_cur[i] = ex;
        }
        carry += sd[1023];
    }
    if (tid == 0) g_off[N_NODES] = carry;
}
__global__ void k_scatter(const int* __restrict__ dst)
{
    int i = blockIdx.x * 256 + threadIdx.x;
    if (i < N_EDGES) {
        int p = atomicAdd(&g_cur[dst[i]], 1);
        g_eids[p] = i;
    }
}

// ---------------- BN finalize (restores g_stats zero invariant) ----------------
__global__ __launch_bounds__(128) void k_bn_final(const float* __restrict__ g,
                                                  const float* __restrict__ b,
                                                  float invc)
{
    int d = threadIdx.x;
    float s = g_stats[d], sq = g_stats[128 + d];
    float mean = s * invc;
    float var = sq * invc - mean * mean;
    float sc = g[d] * rsqrtf(var + EPS_BN);
    g_bn_scale[d] = sc;
    g_bn_shift[d] = b[d] - mean * sc;
    g_stats[d] = 0.f;
    g_stats[128 + d] = 0.f;
}

// ---------------- node GEMM: Ah,Bh,Dh,Eh = h @ W.T + b ----------------
// smem: ahi(34816) alo(34816) whi(34816) = 104448 -> 2 blocks/SM
__global__ __launch_bounds__(512) void k_node_gemm(
    int lay,
    const float* __restrict__ Ba, const float* __restrict__ Bb_,
    const float* __restrict__ Bd, const float* __restrict__ Be)
{
    const float* Bp[4] = {Ba, Bb_, Bd, Be};
    float* Op[4] = {g_Ah, g_Bh, g_Dh, g_Eh};
    extern __shared__ char smc[];
    half* ahi = (half*)smc;
    half* alo = ahi + 128 * SBF;
    half* whi = alo + 128 * SBF;

    int tid = threadIdx.x;
    int lane = tid & 31, w = tid >> 5;
    int m0w = (w & 3) * 32, n0w = (w >> 2) * 32;
    int n0 = blockIdx.x * 128;
    int mlim = N_NODES - n0;
    if (mlim > 128) mlim = 128;

    split_tileA(g_h + (size_t)n0 * 128, mlim, ahi, alo, tid);

    for (int mat = 0; mat < 4; mat++) {
        __syncthreads();
        const uint2* wsrc = (const uint2*)(g_Whi + (size_t)(lay * 5 + mat) * 128 * SBF);
        for (int i = tid; i < (128 * SBF) / 4; i += 512) ((uint2*)whi)[i] = wsrc[i];
        __syncthreads();
        float acc[2][4][4];
#pragma unroll
        for (int ms = 0; ms < 2; ms++)
#pragma unroll
            for (int nt = 0; nt < 4; nt++)
#pragma unroll
                for (int j = 0; j < 4; j++) acc[ms][nt][j] = 0.f;

        mma_mainloop(ahi, alo, whi, m0w, n0w, lane, acc);

        float* Out = Op[mat];
        const float* Bias = Bp[mat];
#pragma unroll
        for (int ms = 0; ms < 2; ms++)
#pragma unroll
            for (int nt = 0; nt < 4; nt++) {
                int col = n0w + nt * 8 + (lane & 3) * 2;
                float2 bv = *(const float2*)(Bias + col);
                int r0 = m0w + ms * 16 + (lane >> 2);
                if (r0 < mlim) {
                    float2 v = {acc[ms][nt][0] + bv.x, acc[ms][nt][1] + bv.y};
                    *(float2*)(Out + (size_t)(n0 + r0) * 128 + col) = v;
                }
                if (r0 + 8 < mlim) {
                    float2 v = {acc[ms][nt][2] + bv.x, acc[ms][nt][3] + bv.y};
                    *(float2*)(Out + (size_t)(n0 + r0 + 8) * 128 + col) = v;
                }
            }
    }
}

// ---------------- edge pass1: ehat = e@Cw.T + Cb + Dh[dst] + Eh[src]; BN stats --------
// smem: tiles 104448 (+Csm aliases ahi/alo after mma) + tail 2048 = 106496 -> 2 blocks/SM
__global__ __launch_bounds__(512) void k_edge_pass1(int lay,
                                                    const float* __restrict__ Cb,
                                                    const int* __restrict__ src,
                                                    const int* __restrict__ dst)
{
    extern __shared__ char smc[];
    half* ahi = (half*)smc;
    half* alo = ahi + 128 * SBF;
    half* whi = alo + 128 * SBF;
    float* Csm = (float*)smc;                     // aliases ahi/alo after mma
    char* tail = smc + 3 * 128 * SBF * 2;
    int* s_src = (int*)tail;
    int* s_dst = s_src + 128;
    float* ssum = (float*)(s_dst + 128);
    float* ssq = ssum + 128;

    int tid = threadIdx.x;
    int lane = tid & 31, w = tid >> 5;
    int m0w = (w & 3) * 32, n0w = (w >> 2) * 32;
    int e0 = blockIdx.x * 128;

    if (tid < 128) {
        s_src[tid] = src[e0 + tid];
        s_dst[tid] = dst[e0 + tid];
        ssum[tid] = 0.f;
        ssq[tid] = 0.f;
    }
    split_tileA(g_e + (size_t)e0 * 128, 128, ahi, alo, tid);
    {
        const uint2* wsrc = (const uint2*)(g_Whi + (size_t)(lay * 5 + 4) * 128 * SBF);
        for (int i = tid; i < (128 * SBF) / 4; i += 512) ((uint2*)whi)[i] = wsrc[i];
    }
    __syncthreads();

    float acc[2][4][4];
#pragma unroll
    for (int ms = 0; ms < 2; ms++)
#pragma unroll
        for (int nt = 0; nt < 4; nt++)
#pragma unroll
            for (int j = 0; j < 4; j++) acc[ms][nt][j] = 0.f;

    mma_mainloop(ahi, alo, whi, m0w, n0w, lane, acc);

    __syncthreads();      // A tiles dead; Csm aliases them
#pragma unroll
    for (int ms = 0; ms < 2; ms++)
#pragma unroll
        for (int nt = 0; nt < 4; nt++) {
            int col = n0w + nt * 8 + (lane & 3) * 2;
            int r0 = m0w + ms * 16 + (lane >> 2);
            *(float2*)(Csm + r0 * SCF + col) = make_float2(acc[ms][nt][0], acc[ms][nt][1]);
            *(float2*)(Csm + (r0 + 8) * SCF + col) = make_float2(acc[ms][nt][2], acc[ms][nt][3]);
        }
    __syncthreads();

    // add Cb + Dh[dst] + Eh[src] in Csm (16 warps x 8 rows), accumulate stats
    int colg = (tid & 31) << 2;
    int r0 = (tid >> 5) << 3;
    float4 cb4 = *(const float4*)(Cb + colg);
    float s0 = 0.f, s1 = 0.f, s2 = 0.f, s3 = 0.f;
    float q0 = 0.f, q1 = 0.f, q2 = 0.f, q3 = 0.f;
#pragma unroll
    for (int j = 0; j < 8; j++) {
        int r = r0 + j;
        float* crow = Csm + r * SCF + colg;
        float4 c = *(const float4*)crow;
        int dd = s_dst[r], sr = s_src[r];
        float4 dh = *(const float4*)(g_Dh + (size_t)dd * 128 + colg);
        float4 eh = *(const float4*)(g_Eh + (size_t)sr * 128 + colg);
        float4 v;
        v.x = c.x + cb4.x + dh.x + eh.x;
        v.y = c.y + cb4.y + dh.y + eh.y;
        v.z = c.z + cb4.z + dh.z + eh.z;
        v.w = c.w + cb4.w + dh.w + eh.w;
        *(float4*)crow = v;
        s0 += v.x; q0 += v.x * v.x;
        s1 += v.y; q1 += v.y * v.y;
        s2 += v.z; q2 += v.z * v.z;
        s3 += v.w; q3 += v.w * v.w;
    }
    atomicAdd(&ssum[colg + 0], s0); atomicAdd(&ssq[colg + 0], q0);
    atomicAdd(&ssum[colg + 1], s1); atomicAdd(&ssq[colg + 1], q1);
    atomicAdd(&ssum[colg + 2], s2); atomicAdd(&ssq[colg + 2], q2);
    atomicAdd(&ssum[colg + 3], s3); atomicAdd(&ssq[colg + 3], q3);
    __syncthreads();

    // coalesced fp16 ehat store
    for (int i = tid; i < 128 * 32; i += 512) {
        int r = i >> 5, c4 = (i & 31) << 2;
        float4 v = *(const float4*)(Csm + r * SCF + c4);
        half2 p0 = __floats2half2_rn(v.x, v.y);
        half2 p1 = __floats2half2_rn(v.z, v.w);
        *(uint2*)(g_ehat + (size_t)(e0 + r) * 128 + c4) =
            make_uint2(*(unsigned*)&p0, *(unsigned*)&p1);
    }
    if (tid < 128) {
        atomicAdd(&g_stats[tid], ssum[tid]);
        atomicAdd(&g_stats[128 + tid], ssq[tid]);
    }
}

// ---------------- fused: e += relu(bn(ehat)); t = Ah + segsum(sig*Bh[src])/(segsum(sig)+eps) --
__global__ __launch_bounds__(128) void k_agg_fused(const int* __restrict__ src)
{
    int n = blockIdx.x;
    int d = threadIdx.x;
    int beg = g_off[n], end = g_off[n + 1];
    float sc = g_bn_scale[d], sh = g_bn_shift[d];
    float num = 0.f, den = 0.f;
    for (int j = beg; j < end; j++) {
        int eid = g_eids[j];
        float x = __half2float(g_ehat[(size_t)eid * 128 + d]);
        float s = 1.f / (1.f + __expf(-x));
        num += s * g_Bh[(size_t)src[eid] * 128 + d];
        den += s;
        g_e[(size_t)eid * 128 + d] += fmaxf(fmaf(x, sc, sh), 0.f);
    }
    float t = g_Ah[n * 128 + d] + num / (den + EPS_AGG);
    g_t[n * 128 + d] = t;
    atomicAdd(&g_stats[d], t);
    atomicAdd(&g_stats[128 + d], t * t);
}

// ---------------- h += relu(bn(t)) ----------------
__global__ __launch_bounds__(256) void k_node_update()
{
    int i = blockIdx.x * 256 + threadIdx.x;
    int d4 = (i & 31) << 2;
    float4 sc = *(const float4*)(g_bn_scale + d4);
    float4 sh = *(const float4*)(g_bn_shift + d4);
    float4 x = ((const float4*)g_t)[i];
    float4 hv = ((const float4*)g_h)[i];
    hv.x += fmaxf(fmaf(x.x, sc.x, sh.x), 0.f);
    hv.y += fmaxf(fmaf(x.y, sc.y, sh.y), 0.f);
    hv.z += fmaxf(fmaf(x.z, sc.z, sh.z), 0.f);
    hv.w += fmaxf(fmaf(x.w, sc.w, sh.w), 0.f);
    ((float4*)g_h)[i] = hv;
}

// ---------------- decoder ----------------
__global__ __launch_bounds__(256) void k_dec(const float* __restrict__ dw,
                                             const float* __restrict__ db,
                                             const int* __restrict__ src,
                                             const int* __restrict__ dst,
                                             float* __restrict__ out)
{
    int w = (blockIdx.x * 256 + threadIdx.x) >> 5;
    if (w >= N_EDGES) return;
    int lane = threadIdx.x & 31;
    int s = src[w], d = dst[w];
    float4 w1 = *(const float4*)(dw + lane * 4);
    float4 w2 = *(const float4*)(dw + 128 + lane * 4);
    float4 w3 = *(const float4*)(dw + 256 + lane * 4);
    float4 hs = *(const float4*)(g_h + (size_t)s * 128 + lane * 4);
    float4 hd = *(const float4*)(g_h + (size_t)d * 128 + lane * 4);
    float4 ee = *(const float4*)(g_e + (size_t)w * 128 + lane * 4);
    float acc = w1.x * hs.x + w1.y * hs.y + w1.z * hs.z + w1.w * hs.w
              + w2.x * hd.x + w2.y * hd.y + w2.z * hd.z + w2.w * hd.w
              + w3.x * ee.x + w3.y * ee.y + w3.z * ee.z + w3.w * ee.w;
#pragma unroll
    for (int ofs = 16; ofs > 0; ofs >>= 1) acc += __shfl_down_sync(0xffffffffu, acc, ofs);
    if (lane == 0) out[w] = acc + db[0];
}

// ---------------- launcher ----------------
extern "C" void kernel_launch(void* const* d_in, const int* in_sizes, int n_in,
                              void* d_out, int out_size)
{
    const float* emb    = (const float*)d_in[0];
    const float* conv_w = (const float*)d_in[1];
    const float* conv_b = (const float*)d_in[2];
    const float* ee_w   = (const float*)d_in[3];
    const float* ee_b   = (const float*)d_in[4];
    const float* Aw     = (const float*)d_in[5];
    const float* Ab     = (const float*)d_in[6];
    const float* Bw     = (const float*)d_in[7];
    const float* Bb     = (const float*)d_in[8];
    const float* Cw     = (const float*)d_in[9];
    const float* Cb     = (const float*)d_in[10];
    const float* Dw     = (const float*)d_in[11];
    const float* Db     = (const float*)d_in[12];
    const float* Ew     = (const float*)d_in[13];
    const float* Eb     = (const float*)d_in[14];
    const float* bnh_g  = (const float*)d_in[15];
    const float* bnh_b  = (const float*)d_in[16];
    const float* bne_g  = (const float*)d_in[17];
    const float* bne_b  = (const float*)d_in[18];
    const float* dec_w  = (const float*)d_in[19];
    const float* dec_b  = (const float*)d_in[20];
    const float* sim    = (const float*)d_in[21];
    const float* length = (const float*)d_in[22];
    const int*   reads  = (const int*)d_in[23];
    const int*   src    = (const int*)d_in[24];
    const int*   dst    = (const int*)d_in[25];
    float* out = (float*)d_out;

    const int smemG = 3 * 128 * SBF * 2;                  // 104448 -> 2 blocks/SM
    const int smemE = smemG + 2048;                        // 106496 -> 2 blocks/SM
    const int smemS = (10 * 16 * DIM) * 4 + 2 * 512 * 4;   // 86016
    cudaFuncSetAttribute(k_node_gemm, cudaFuncAttributeMaxDynamicSharedMemorySize, smemG);
    cudaFuncSetAttribute(k_edge_pass1, cudaFuncAttributeMaxDynamicSharedMemorySize, smemE);
    cudaFuncSetAttribute(k_seq, cudaFuncAttributeMaxDynamicSharedMemorySize, smemS);

    const float invE = 1.f / (float)N_EDGES;
    const float invN = 1.f / (float)N_NODES;

    k_prep<<<60, 256>>>(emb, conv_w, Aw, Bw, Cw, Dw, Ew);               // 0
    k_W2<<<(10 * 16 * DIM + 255) / 256, 256>>>();                       // 1
    k_seq<<<N_NODES / 8, 512, smemS>>>(reads, conv_b);                  // 2
    k_node_gemm<<<(N_NODES + 127) / 128, 512, smemG>>>(                 // 3 <- profiled
        0, Ab, Bb, Db, Eb);
    k_edge_enc<<<N_EDGES / 32, 128>>>(sim, length, ee_w, ee_b);         // 4
    k_edge_pass1<<<N_EDGES / 128, 512, smemE>>>(0, Cb, src, dst);       // 5

    k_csr_zero<<<(N_NODES + 255) / 256, 256>>>();
    k_hist<<<N_EDGES / 256, 256>>>(dst);
    k_scan<<<1, 1024>>>();
    k_scatter<<<N_EDGES / 256, 256>>>(dst);

    k_bn_final<<<1, 128>>>(bne_g, bne_b, invE);
    k_agg_fused<<<N_NODES, 128>>>(src);
    k_bn_final<<<1, 128>>>(bnh_g, bnh_b, invN);
    k_node_update<<<(N_NODES * 32) / 256, 256>>>();

    for (int i = 1; i < N_LAYERS; i++) {
        const int bo = i * DIM;
        k_node_gemm<<<(N_NODES + 127) / 128, 512, smemG>>>(
            i, Ab + bo, Bb + bo, Db + bo, Eb + bo);
        k_edge_pass1<<<N_EDGES / 128, 512, smemE>>>(i, Cb + bo, src, dst);
        k_bn_final<<<1, 128>>>(bne_g + bo, bne_b + bo, invE);
        k_agg_fused<<<N_NODES, 128>>>(src);
        k_bn_final<<<1, 128>>>(bnh_g + bo, bnh_b + bo, invN);
        k_node_update<<<(N_NODES * 32) / 256, 256>>>();
    }
    k_dec<<<(N_EDGES * 32 + 255) / 256, 256>>>(dec_w, dec_b, src, dst, out);
}

// round 10
// speedup vs baseline: 1.7382x; 1.0145x over previous
#include <cuda_runtime.h>
#include <cuda_fp16.h>
#include <cstdint>

#define N_NODES 20000
#define READ_LEN 64
#define N_EDGES 320000
#define DIM 128
#define KSZ 20
#define CONV_T (READ_LEN - KSZ + 1)
#define N_LAYERS 4
#define EPS_BN 1e-5f
#define EPS_AGG 1e-6f

#define SBF 136   // half smem row stride (272B): 16B-aligned rows, ldsm conflict-free
#define SCF 132   // fp32 C smem row stride

// ---------------- device scratch ----------------
__device__ float g_h[N_NODES * DIM];
__device__ float g_e[(size_t)N_EDGES * DIM];
__device__ half  g_ehat[(size_t)N_EDGES * DIM];      // fp16 ehat
__device__ float g_Ah[N_NODES * DIM];
__device__ float g_Bh[N_NODES * DIM];
__device__ float g_Dh[N_NODES * DIM];
__device__ float g_Eh[N_NODES * DIM];
__device__ float g_t[N_NODES * DIM];
__device__ float g_wsum[4 * KSZ * DIM];
__device__ float g_W2[10 * 16 * DIM];
__device__ half  g_Whi[20 * 128 * SBF];              // pre-split weights (smem image)
__device__ float g_stats[2 * DIM];                   // zero-init; bn_final restores zeros
__device__ float g_bn_scale[DIM];
__device__ float g_bn_shift[DIM];
__device__ int g_cnt[N_NODES];
__device__ int g_off[N_NODES + 1];
__device__ int g_cur[N_NODES];
__device__ int g_eids[N_EDGES];

// ---------------- mma helpers ----------------
__device__ __forceinline__ unsigned s2u(const void* p)
{
    return (unsigned)__cvta_generic_to_shared(p);
}
__device__ __forceinline__ void ldsm4(unsigned* r, unsigned addr)
{
    asm volatile("ldmatrix.sync.aligned.m8n8.x4.shared.b16 {%0,%1,%2,%3}, [%4];"
                 : "=r"(r[0]), "=r"(r[1]), "=r"(r[2]), "=r"(r[3]) : "r"(addr));
}
__device__ __forceinline__ void mma16816(float* c, const unsigned* a, const unsigned* b)
{
    asm volatile("mma.sync.aligned.m16n8k16.row.col.f32.f16.f16.f32 "
                 "{%0,%1,%2,%3}, {%4,%5,%6,%7}, {%8,%9}, {%0,%1,%2,%3};"
                 : "+f"(c[0]), "+f"(c[1]), "+f"(c[2]), "+f"(c[3])
                 : "r"(a[0]), "r"(a[1]), "r"(a[2]), "r"(a[3]), "r"(b[0]), "r"(b[1]));
}

// split fp32 tile [rows<=128][128] into hi/lo fp16 smem tiles (512 threads)
__device__ __forceinline__ void split_tileA(const float* __restrict__ g, int rows,
                                            half* hi, half* lo, int tid)
{
#pragma unroll
    for (int i = tid; i < 128 * 32; i += 512) {
        int r = i >> 5, c = (i & 31) << 2;
        float4 v = make_float4(0.f, 0.f, 0.f, 0.f);
        if (r < rows) v = *(const float4*)(g + r * 128 + c);
        half hx = __float2half_rn(v.x), hy = __float2half_rn(v.y);
        half hz = __float2half_rn(v.z), hw = __float2half_rn(v.w);
        half2 hp0 = __halves2half2(hx, hy), hp1 = __halves2half2(hz, hw);
        half2 lp0 = __floats2half2_rn(v.x - __half2float(hx), v.y - __half2float(hy));
        half2 lp1 = __floats2half2_rn(v.z - __half2float(hz), v.w - __half2float(hw));
        *(uint2*)(hi + r * SBF + c) = make_uint2(*(unsigned*)&hp0, *(unsigned*)&hp1);
        *(uint2*)(lo + r * SBF + c) = make_uint2(*(unsigned*)&lp0, *(unsigned*)&lp1);
    }
}

// mainloop (per warp, 32x32 tile): acc += Ahi*Whi + Alo*Whi
// A-fragments are reused between the hi and lo passes to keep regs <= 64.
__device__ __forceinline__ void mma_mainloop(const half* ahi, const half* alo,
                                             const half* whi,
                                             int m0w, int n0w, int lane,
                                             float acc[2][4][4])
{
    int aoff = (lane & 15) * SBF + (lane >> 4) * 8;
    int boff = ((lane & 7) + ((lane >> 4) << 3)) * SBF + ((lane >> 3) & 1) * 8;
#pragma unroll
    for (int kt = 0; kt < 8; kt++) {
        unsigned bf[2][4];
#pragma unroll
        for (int np = 0; np < 2; np++) {
            int o = (n0w + np * 16) * SBF + boff + kt * 16;
            ldsm4(bf[np], s2u(whi + o));
        }
        unsigned af[2][4];
#pragma unroll
        for (int ms = 0; ms < 2; ms++) {
            int o = (m0w + ms * 16) * SBF + aoff + kt * 16;
            ldsm4(af[ms], s2u(ahi + o));
        }
#pragma unroll
        for (int ms = 0; ms < 2; ms++)
#pragma unroll
            for (int nt = 0; nt < 4; nt++)
                mma16816(acc[ms][nt], af[ms], &bf[nt >> 1][(nt & 1) * 2]);
#pragma unroll
        for (int ms = 0; ms < 2; ms++) {
            int o = (m0w + ms * 16) * SBF + aoff + kt * 16;
            ldsm4(af[ms], s2u(alo + o));      // overwrite hi frags
        }
#pragma unroll
        for (int ms = 0; ms < 2; ms++)
#pragma unroll
            for (int nt = 0; nt < 4; nt++)
                mma16816(acc[ms][nt], af[ms], &bf[nt >> 1][(nt & 1) * 2]);
    }
}

// ---------------- prep: conv wsum + weight pre-split ----------------
__global__ void k_prep(const float* __restrict__ emb, const float* __restrict__ cw,
                       const float* __restrict__ Aw, const float* __restrict__ Bw,
                       const float* __restrict__ Cw, const float* __restrict__ Dw,
                       const float* __restrict__ Ew)
{
    int bx = blockIdx.x, tid = threadIdx.x;
    if (bx < 40) {
        int idx = bx * 256 + tid;
        if (idx >= 4 * KSZ * DIM) return;
        int d = idx & 127;
        int bk = idx >> 7;
        int k = bk % KSZ, b = bk / KSZ;
        float s = 0.f;
#pragma unroll
        for (int c = 0; c < 3; c++) s += emb[b * 3 + c] * cw[d * 3 * KSZ + c * KSZ + k];
        g_wsum[idx] = s;
    } else {
        int m = bx - 40;             // 0..19
        int lay = m / 5, which = m % 5;
        const float* srcs[5] = {Aw, Bw, Dw, Ew, Cw};
        const float* src = srcs[which] + lay * DIM * DIM;
        half* dst = g_Whi + (size_t)m * 128 * SBF;
        for (int i = tid; i < 128 * 128; i += 256) {
            int r = i >> 7, c = i & 127;
            dst[r * SBF + c] = __float2half_rn(src[i]);
        }
    }
}

__global__ void k_W2()
{
    int idx = blockIdx.x * 256 + threadIdx.x;
    if (idx >= 10 * 16 * DIM) return;
    int d = idx & 127;
    int r = idx >> 7;
    int c2 = r & 15, k2 = r >> 4;
    int a = c2 >> 2, b = c2 & 3;
    g_W2[idx] = g_wsum[(a * KSZ + 2 * k2) * DIM + d] + g_wsum[(b * KSZ + 2 * k2 + 1) * DIM + d];
}

__global__ __launch_bounds__(512) void k_seq(const int* __restrict__ reads,
                                             const float* __restrict__ conv_b)
{
    extern __shared__ float sm[];
    float* sW2 = sm;
    int* scode = (int*)(sm + 10 * 16 * DIM);
    int* spc = scode + 512;
    int tid = threadIdx.x;

    for (int i = tid; i < (10 * 16 * DIM) / 4; i += 512)
        ((float4*)sW2)[i] = ((const float4*)g_W2)[i];

    int nl = tid >> 6, l = tid & 63;
    int n = blockIdx.x * 8 + nl;
    scode[tid] = reads[n * READ_LEN + l];
    __syncthreads();
    if (l < 63) spc[tid] = (scode[tid] * 4 + scode[tid + 1]) << 7;
    __syncthreads();

    int dp = tid & 63;
    const float* wd = sW2 + dp * 2;
    const int* pc = spc + nl * 64;
    float m0 = -3.4e38f, m1 = -3.4e38f;
#pragma unroll
    for (int t = 0; t < CONV_T; t++) {
        float s0 = 0.f, s1 = 0.f;
#pragma unroll
        for (int k2 = 0; k2 < 10; k2++) {
            float2 v = *(const float2*)(wd + pc[t + 2 * k2] + k2 * 2048);
            s0 += v.x; s1 += v.y;
        }
        m0 = fmaxf(m0, s0);
        m1 = fmaxf(m1, s1);
    }
    float2 bv = *(const float2*)(conv_b + dp * 2);
    float2 hv;
    hv.x = fmaxf(m0 + bv.x, 0.f);
    hv.y = fmaxf(m1 + bv.y, 0.f);
    *(float2*)(g_h + n * DIM + dp * 2) = hv;
}

// ---------------- edge encoder ----------------
__global__ __launch_bounds__(128) void k_edge_enc(const float* __restrict__ sim,
                                                  const float* __restrict__ len,
                                                  const float* __restrict__ ew,
                                                  const float* __restrict__ eb)
{
    int d = threadIdx.x;
    float w0 = ew[d * 2], w1 = ew[d * 2 + 1], b = eb[d];
    int e0 = blockIdx.x * 32;
#pragma unroll 4
    for (int j = 0; j < 32; j++) {
        int eid = e0 + j;
        g_e[(size_t)eid * DIM + d] = fmaf(sim[eid], w0, fmaf(len[eid], w1, b));
    }
}

// ---------------- CSR build by dst ----------------
__global__ void k_csr_zero()
{
    int i = blockIdx.x * 256 + threadIdx.x;
    if (i < N_NODES) g_cnt[i] = 0;
}
__global__ void k_hist(const int* __restrict__ dst)
{
    int i = blockIdx.x * 256 + threadIdx.x;
    if (i < N_EDGES) atomicAdd(&g_cnt[dst[i]], 1);
}
__global__ __launch_bounds__(1024) void k_scan()
{
    __shared__ int sd[1024];
    int tid = threadIdx.x;
    int carry = 0;
    for (int base = 0; base < N_NODES; base += 1024) {
        int i = base + tid;
        int v = (i < N_NODES) ? g_cnt[i] : 0;
        __syncthreads();
        sd[tid] = v;
        __syncthreads();
        for (int ofs = 1; ofs < 1024; ofs <<= 1) {
            int t = (tid >= ofs) ? sd[tid - ofs] : 0;
            __syncthreads();
            sd[tid] += t;
            __syncthreads();
        }
        if (i < N_NODES) {
            int ex = carry + sd[tid] - v;
            g_off[i] = ex;
            g_cur[i] = ex;
        }
        carry += sd[1023];
    }
    if (tid == 0) g_off[N_NODES] = carry;
}
__global__ void k_scatter(const int* __restrict__ dst)
{
    int i = blockIdx.x * 256 + threadIdx.x;
    if (i < N_EDGES) {
        int p = atomicAdd(&g_cur[dst[i]], 1);
        g_eids[p] = i;
    }
}

// ---------------- BN finalize (restores g_stats zero invariant) ----------------
__global__ __launch_bounds__(128) void k_bn_final(const float* __restrict__ g,
                                                  const float* __restrict__ b,
                                                  float invc)
{
    int d = threadIdx.x;
    float s = g_stats[d], sq = g_stats[128 + d];
    float mean = s * invc;
    float var = sq * invc - mean * mean;
    float sc = g[d] * rsqrtf(var + EPS_BN);
    g_bn_scale[d] = sc;
    g_bn_shift[d] = b[d] - mean * sc;
    g_stats[d] = 0.f;
    g_stats[128 + d] = 0.f;
}

// ---------------- node GEMM: Ah,Bh,Dh,Eh = h @ W.T + b ----------------
// smem 104448, 2 blocks/SM forced (regs capped at 64)
__global__ __launch_bounds__(512, 2) void k_node_gemm(
    int lay,
    const float* __restrict__ Ba, const float* __restrict__ Bb_,
    const float* __restrict__ Bd, const float* __restrict__ Be)
{
    const float* Bp[4] = {Ba, Bb_, Bd, Be};
    float* Op[4] = {g_Ah, g_Bh, g_Dh, g_Eh};
    extern __shared__ char smc[];
    half* ahi = (half*)smc;
    half* alo = ahi + 128 * SBF;
    half* whi = alo + 128 * SBF;

    int tid = threadIdx.x;
    int lane = tid & 31, w = tid >> 5;
    int m0w = (w & 3) * 32, n0w = (w >> 2) * 32;
    int n0 = blockIdx.x * 128;
    int mlim = N_NODES - n0;
    if (mlim > 128) mlim = 128;

    split_tileA(g_h + (size_t)n0 * 128, mlim, ahi, alo, tid);

    for (int mat = 0; mat < 4; mat++) {
        __syncthreads();
        const uint2* wsrc = (const uint2*)(g_Whi + (size_t)(lay * 5 + mat) * 128 * SBF);
        for (int i = tid; i < (128 * SBF) / 4; i += 512) ((uint2*)whi)[i] = wsrc[i];
        __syncthreads();
        float acc[2][4][4];
#pragma unroll
        for (int ms = 0; ms < 2; ms++)
#pragma unroll
            for (int nt = 0; nt < 4; nt++)
#pragma unroll
                for (int j = 0; j < 4; j++) acc[ms][nt][j] = 0.f;

        mma_mainloop(ahi, alo, whi, m0w, n0w, lane, acc);

        float* Out = Op[mat];
        const float* Bias = Bp[mat];
#pragma unroll
        for (int ms = 0; ms < 2; ms++)
#pragma unroll
            for (int nt = 0; nt < 4; nt++) {
                int col = n0w + nt * 8 + (lane & 3) * 2;
                float2 bv = *(const float2*)(Bias + col);
                int r0 = m0w + ms * 16 + (lane >> 2);
                if (r0 < mlim) {
                    float2 v = {acc[ms][nt][0] + bv.x, acc[ms][nt][1] + bv.y};
                    *(float2*)(Out + (size_t)(n0 + r0) * 128 + col) = v;
                }
                if (r0 + 8 < mlim) {
                    float2 v = {acc[ms][nt][2] + bv.x, acc[ms][nt][3] + bv.y};
                    *(float2*)(Out + (size_t)(n0 + r0 + 8) * 128 + col) = v;
                }
            }
    }
}

// ---------------- edge pass1: ehat = e@Cw.T + Cb + Dh[dst] + Eh[src]; BN stats --------
// smem 106496, 2 blocks/SM forced
__global__ __launch_bounds__(512, 2) void k_edge_pass1(int lay,
                                                       const float* __restrict__ Cb,
                                                       const int* __restrict__ src,
                                                       const int* __restrict__ dst)
{
    extern __shared__ char smc[];
    half* ahi = (half*)smc;
    half* alo = ahi + 128 * SBF;
    half* whi = alo + 128 * SBF;
    float* Csm = (float*)smc;                     // aliases ahi/alo after mma
    char* tail = smc + 3 * 128 * SBF * 2;
    int* s_src = (int*)tail;
    int* s_dst = s_src + 128;
    float* ssum = (float*)(s_dst + 128);
    float* ssq = ssum + 128;

    int tid = threadIdx.x;
    int lane = tid & 31, w = tid >> 5;
    int m0w = (w & 3) * 32, n0w = (w >> 2) * 32;
    int e0 = blockIdx.x * 128;

    if (tid < 128) {
        s_src[tid] = src[e0 + tid];
        s_dst[tid] = dst[e0 + tid];
        ssum[tid] = 0.f;
        ssq[tid] = 0.f;
    }
    split_tileA(g_e + (size_t)e0 * 128, 128, ahi, alo, tid);
    {
        const uint2* wsrc = (const uint2*)(g_Whi + (size_t)(lay * 5 + 4) * 128 * SBF);
        for (int i = tid; i < (128 * SBF) / 4; i += 512) ((uint2*)whi)[i] = wsrc[i];
    }
    __syncthreads();

    float acc[2][4][4];
#pragma unroll
    for (int ms = 0; ms < 2; ms++)
#pragma unroll
        for (int nt = 0; nt < 4; nt++)
#pragma unroll
            for (int j = 0; j < 4; j++) acc[ms][nt][j] = 0.f;

    mma_mainloop(ahi, alo, whi, m0w, n0w, lane, acc);

    __syncthreads();      // A tiles dead; Csm aliases them
#pragma unroll
    for (int ms = 0; ms < 2; ms++)
#pragma unroll
        for (int nt = 0; nt < 4; nt++) {
            int col = n0w + nt * 8 + (lane & 3) * 2;
            int r0 = m0w + ms * 16 + (lane >> 2);
            *(float2*)(Csm + r0 * SCF + col) = make_float2(acc[ms][nt][0], acc[ms][nt][1]);
            *(float2*)(Csm + (r0 + 8) * SCF + col) = make_float2(acc[ms][nt][2], acc[ms][nt][3]);
        }
    __syncthreads();

    // add Cb + Dh[dst] + Eh[src] in Csm (16 warps x 8 rows), accumulate stats
    int colg = (tid & 31) << 2;
    int r0 = (tid >> 5) << 3;
    float4 cb4 = *(const float4*)(Cb + colg);
    float s0 = 0.f, s1 = 0.f, s2 = 0.f, s3 = 0.f;
    float q0 = 0.f, q1 = 0.f, q2 = 0.f, q3 = 0.f;
#pragma unroll
    for (int j = 0; j < 8; j++) {
        int r = r0 + j;
        float* crow = Csm + r * SCF + colg;
        float4 c = *(const float4*)crow;
        int dd = s_dst[r], sr = s_src[r];
        float4 dh = *(const float4*)(g_Dh + (size_t)dd * 128 + colg);
        float4 eh = *(const float4*)(g_Eh + (size_t)sr * 128 + colg);
        float4 v;
        v.x = c.x + cb4.x + dh.x + eh.x;
        v.y = c.y + cb4.y + dh.y + eh.y;
        v.z = c.z + cb4.z + dh.z + eh.z;
        v.w = c.w + cb4.w + dh.w + eh.w;
        *(float4*)crow = v;
        s0 += v.x; q0 += v.x * v.x;
        s1 += v.y; q1 += v.y * v.y;
        s2 += v.z; q2 += v.z * v.z;
        s3 += v.w; q3 += v.w * v.w;
    }
    atomicAdd(&ssum[colg + 0], s0); atomicAdd(&ssq[colg + 0], q0);
    atomicAdd(&ssum[colg + 1], s1); atomicAdd(&ssq[colg + 1], q1);
    atomicAdd(&ssum[colg + 2], s2); atomicAdd(&ssq[colg + 2], q2);
    atomicAdd(&ssum[colg + 3], s3); atomicAdd(&ssq[colg + 3], q3);
    __syncthreads();

    // coalesced fp16 ehat store
    for (int i = tid; i < 128 * 32; i += 512) {
        int r = i >> 5, c4 = (i & 31) << 2;
        float4 v = *(const float4*)(Csm + r * SCF + c4);
        half2 p0 = __floats2half2_rn(v.x, v.y);
        half2 p1 = __floats2half2_rn(v.z, v.w);
        *(uint2*)(g_ehat + (size_t)(e0 + r) * 128 + c4) =
            make_uint2(*(unsigned*)&p0, *(unsigned*)&p1);
    }
    if (tid < 128) {
        atomicAdd(&g_stats[tid], ssum[tid]);
        atomicAdd(&g_stats[128 + tid], ssq[tid]);
    }
}

// ---------------- fused: e += relu(bn(ehat)); t = Ah + segsum(sig*Bh[src])/(segsum(sig)+eps) --
__global__ __launch_bounds__(128) void k_agg_fused(const int* __restrict__ src)
{
    int n = blockIdx.x;
    int d = threadIdx.x;
    int beg = g_off[n], end = g_off[n + 1];
    float sc = g_bn_scale[d], sh = g_bn_shift[d];
    float num = 0.f, den = 0.f;
    for (int j = beg; j < end; j++) {
        int eid = g_eids[j];
        float x = __half2float(g_ehat[(size_t)eid * 128 + d]);
        float s = 1.f / (1.f + __expf(-x));
        num += s * g_Bh[(size_t)src[eid] * 128 + d];
        den += s;
        g_e[(size_t)eid * 128 + d] += fmaxf(fmaf(x, sc, sh), 0.f);
    }
    float t = g_Ah[n * 128 + d] + num / (den + EPS_AGG);
    g_t[n * 128 + d] = t;
    atomicAdd(&g_stats[d], t);
    atomicAdd(&g_stats[128 + d], t * t);
}

// ---------------- h += relu(bn(t)) ----------------
__global__ __launch_bounds__(256) void k_node_update()
{
    int i = blockIdx.x * 256 + threadIdx.x;
    int d4 = (i & 31) << 2;
    float4 sc = *(const float4*)(g_bn_scale + d4);
    float4 sh = *(const float4*)(g_bn_shift + d4);
    float4 x = ((const float4*)g_t)[i];
    float4 hv = ((const float4*)g_h)[i];
    hv.x += fmaxf(fmaf(x.x, sc.x, sh.x), 0.f);
    hv.y += fmaxf(fmaf(x.y, sc.y, sh.y), 0.f);
    hv.z += fmaxf(fmaf(x.z, sc.z, sh.z), 0.f);
    hv.w += fmaxf(fmaf(x.w, sc.w, sh.w), 0.f);
    ((float4*)g_h)[i] = hv;
}

// ---------------- decoder ----------------
__global__ __launch_bounds__(256) void k_dec(const float* __restrict__ dw,
                                             const float* __restrict__ db,
                                             const int* __restrict__ src,
                                             const int* __restrict__ dst,
                                             float* __restrict__ out)
{
    int w = (blockIdx.x * 256 + threadIdx.x) >> 5;
    if (w >= N_EDGES) return;
    int lane = threadIdx.x & 31;
    int s = src[w], d = dst[w];
    float4 w1 = *(const float4*)(dw + lane * 4);
    float4 w2 = *(const float4*)(dw + 128 + lane * 4);
    float4 w3 = *(const float4*)(dw + 256 + lane * 4);
    float4 hs = *(const float4*)(g_h + (size_t)s * 128 + lane * 4);
    float4 hd = *(const float4*)(g_h + (size_t)d * 128 + lane * 4);
    float4 ee = *(const float4*)(g_e + (size_t)w * 128 + lane * 4);
    float acc = w1.x * hs.x + w1.y * hs.y + w1.z * hs.z + w1.w * hs.w
              + w2.x * hd.x + w2.y * hd.y + w2.z * hd.z + w2.w * hd.w
              + w3.x * ee.x + w3.y * ee.y + w3.z * ee.z + w3.w * ee.w;
#pragma unroll
    for (int ofs = 16; ofs > 0; ofs >>= 1) acc += __shfl_down_sync(0xffffffffu, acc, ofs);
    if (lane == 0) out[w] = acc + db[0];
}

// ---------------- launcher ----------------
extern "C" void kernel_launch(void* const* d_in, const int* in_sizes, int n_in,
                              void* d_out, int out_size)
{
    const float* emb    = (const float*)d_in[0];
    const float* conv_w = (const float*)d_in[1];
    const float* conv_b = (const float*)d_in[2];
    const float* ee_w   = (const float*)d_in[3];
    const float* ee_b   = (const float*)d_in[4];
    const float* Aw     = (const float*)d_in[5];
    const float* Ab     = (const float*)d_in[6];
    const float* Bw     = (const float*)d_in[7];
    const float* Bb     = (const float*)d_in[8];
    const float* Cw     = (const float*)d_in[9];
    const float* Cb     = (const float*)d_in[10];
    const float* Dw     = (const float*)d_in[11];
    const float* Db     = (const float*)d_in[12];
    const float* Ew     = (const float*)d_in[13];
    const float* Eb     = (const float*)d_in[14];
    const float* bnh_g  = (const float*)d_in[15];
    const float* bnh_b  = (const float*)d_in[16];
    const float* bne_g  = (const float*)d_in[17];
    const float* bne_b  = (const float*)d_in[18];
    const float* dec_w  = (const float*)d_in[19];
    const float* dec_b  = (const float*)d_in[20];
    const float* sim    = (const float*)d_in[21];
    const float* length = (const float*)d_in[22];
    const int*   reads  = (const int*)d_in[23];
    const int*   src    = (const int*)d_in[24];
    const int*   dst    = (const int*)d_in[25];
    float* out = (float*)d_out;

    const int smemG = 3 * 128 * SBF * 2;                  // 104448 -> 2 blocks/SM
    const int smemE = smemG + 2048;                        // 106496 -> 2 blocks/SM
    const int smemS = (10 * 16 * DIM) * 4 + 2 * 512 * 4;   // 86016
    cudaFuncSetAttribute(k_node_gemm, cudaFuncAttributeMaxDynamicSharedMemorySize, smemG);
    cudaFuncSetAttribute(k_edge_pass1, cudaFuncAttributeMaxDynamicSharedMemorySize, smemE);
    cudaFuncSetAttribute(k_seq, cudaFuncAttributeMaxDynamicSharedMemorySize, smemS);

    const float invE = 1.f / (float)N_EDGES;
    const float invN = 1.f / (float)N_NODES;

    k_prep<<<60, 256>>>(emb, conv_w, Aw, Bw, Cw, Dw, Ew);               // 0
    k_W2<<<(10 * 16 * DIM + 255) / 256, 256>>>();                       // 1
    k_seq<<<N_NODES / 8, 512, smemS>>>(reads, conv_b);                  // 2
    k_node_gemm<<<(N_NODES + 127) / 128, 512, smemG>>>(                 // 3 <- profiled
        0, Ab, Bb, Db, Eb);
    k_edge_enc<<<N_EDGES / 32, 128>>>(sim, length, ee_w, ee_b);         // 4
    k_edge_pass1<<<N_EDGES / 128, 512, smemE>>>(0, Cb, src, dst);       // 5

    k_csr_zero<<<(N_NODES + 255) / 256, 256>>>();
    k_hist<<<N_EDGES / 256, 256>>>(dst);
    k_scan<<<1, 1024>>>();
    k_scatter<<<N_EDGES / 256, 256>>>(dst);

    k_bn_final<<<1, 128>>>(bne_g, bne_b, invE);
    k_agg_fused<<<N_NODES, 128>>>(src);
    k_bn_final<<<1, 128>>>(bnh_g, bnh_b, invN);
    k_node_update<<<(N_NODES * 32) / 256, 256>>>();

    for (int i = 1; i < N_LAYERS; i++) {
        const int bo = i * DIM;
        k_node_gemm<<<(N_NODES + 127) / 128, 512, smemG>>>(
            i, Ab + bo, Bb + bo, Db + bo, Eb + bo);
        k_edge_pass1<<<N_EDGES / 128, 512, smemE>>>(i, Cb + bo, src, dst);
        k_bn_final<<<1, 128>>>(bne_g + bo, bne_b + bo, invE);
        k_agg_fused<<<N_NODES, 128>>>(src);
        k_bn_final<<<1, 128>>>(bnh_g + bo, bnh_b + bo, invN);
        k_node_update<<<(N_NODES * 32) / 256, 256>>>();
    }
    k_dec<<<(N_EDGES * 32 + 255) / 256, 256>>>(dec_w, dec_b, src, dst, out);
}